// round 3
// baseline (speedup 1.0000x reference)
#include <cuda_runtime.h>
#include <cstdint>
#include <cstddef>

#define BB    8
#define HH    8
#define NQ    1024
#define NKV   1024
#define DHD   64
#define DM    512
#define BHN   (BB*HH)   // 64

typedef unsigned long long ull;

// packed f32x2 FMA: c = a*b + c  (sm_103a FFMA2)
#define FMA2(c,a,b) asm("fma.rn.f32x2 %0, %1, %2, %0;" : "+l"(c) : "l"(a), "l"(b))

__device__ __forceinline__ ull dup2(float x) {
    ull r; unsigned u = __float_as_uint(x);
    asm("mov.b64 %0, {%1, %1};" : "=l"(r) : "r"(u));
    return r;
}
__device__ __forceinline__ float2 unpk(ull v) {
    unsigned lo, hi;
    asm("mov.b64 {%0, %1}, %2;" : "=r"(lo), "=r"(hi) : "l"(v));
    return make_float2(__uint_as_float(lo), __uint_as_float(hi));
}

// ---------------- device scratch ----------------
__device__ float g_Qh[(size_t)BHN*NQ*DHD];
__device__ float g_Kh[(size_t)BHN*NKV*DHD];
__device__ float g_Vh[(size_t)BHN*NKV*DHD];
__device__ float g_Sb[(size_t)NQ*BHN*NKV];
__device__ float g_ctx[(size_t)BB*NQ*DM];
__device__ float g_attn_fallback[(size_t)BHN*NQ*NKV];

// =====================================================================
// Kernel 1/4: C[M,512] = A[M,512] @ W[512,512] + bias (f32x2 core)
// 128x128 tile, BK=8, 256 thr, 8 rows x 8 cols per thread (cols split
// as {nc*4..+3} and {64+nc*4..+3} for conflict-free LDS).
// =====================================================================
__global__ __launch_bounds__(256) void proj_gemm(
    const float* __restrict__ A, const float* __restrict__ W,
    const float* __restrict__ bias, float* __restrict__ C, int permute)
{
    const int K = 512, N = 512;
    __shared__ float As2[8][260];   // a-rows duplicated: [k][2*row]
    __shared__ float Ws[8][128];
    int tid  = threadIdx.x;
    int cRow = blockIdx.y, cCol = blockIdx.x;
    int aRow = tid >> 1;            // 0..127
    int aCol = (tid & 1) << 2;      // 0 or 4
    int wRow = tid >> 5;            // 0..7
    int wCol = (tid & 31) << 2;     // 0..124
    int tRow = (tid >> 4) << 3;     // 0..120
    int nc   = tid & 15;            // 0..15

    const float* Ap = A + (size_t)(cRow*128 + aRow)*K + aCol;
    const float* Wp = W + (size_t)wRow*N + cCol*128 + wCol;

    ull acc[8][4];
#pragma unroll
    for (int i = 0; i < 8; i++)
#pragma unroll
        for (int j = 0; j < 4; j++) acc[i][j] = 0ULL;

    for (int kb = 0; kb < K; kb += 8) {
        float4 a4 = *(const float4*)(Ap + kb);
        As2[aCol+0][aRow*2] = a4.x; As2[aCol+0][aRow*2+1] = a4.x;
        As2[aCol+1][aRow*2] = a4.y; As2[aCol+1][aRow*2+1] = a4.y;
        As2[aCol+2][aRow*2] = a4.z; As2[aCol+2][aRow*2+1] = a4.z;
        As2[aCol+3][aRow*2] = a4.w; As2[aCol+3][aRow*2+1] = a4.w;
        *(float4*)&Ws[wRow][wCol] = *(const float4*)(Wp + (size_t)kb*N);
        __syncthreads();
#pragma unroll
        for (int kk = 0; kk < 8; kk++) {
            ulonglong2 A0 = *(const ulonglong2*)&As2[kk][tRow*2];
            ulonglong2 A1 = *(const ulonglong2*)&As2[kk][tRow*2 + 4];
            ulonglong2 A2 = *(const ulonglong2*)&As2[kk][tRow*2 + 8];
            ulonglong2 A3 = *(const ulonglong2*)&As2[kk][tRow*2 + 12];
            ulonglong2 B0 = *(const ulonglong2*)&Ws[kk][nc*4];
            ulonglong2 B1 = *(const ulonglong2*)&Ws[kk][64 + nc*4];
            ull av[8] = {A0.x, A0.y, A1.x, A1.y, A2.x, A2.y, A3.x, A3.y};
#pragma unroll
            for (int i = 0; i < 8; i++) {
                FMA2(acc[i][0], av[i], B0.x);
                FMA2(acc[i][1], av[i], B0.y);
                FMA2(acc[i][2], av[i], B1.x);
                FMA2(acc[i][3], av[i], B1.y);
            }
        }
        __syncthreads();
    }

    int colA = cCol*128 + nc*4;
    int colB = colA + 64;
    float4 bA = *(const float4*)&bias[colA];
    float4 bB = *(const float4*)&bias[colB];

#pragma unroll
    for (int i = 0; i < 8; i++) {
        int m = cRow*128 + tRow + i;
        float2 p0 = unpk(acc[i][0]), p1 = unpk(acc[i][1]);
        float2 p2 = unpk(acc[i][2]), p3 = unpk(acc[i][3]);
        float4 vA = make_float4(p0.x + bA.x, p0.y + bA.y, p1.x + bA.z, p1.y + bA.w);
        float4 vB = make_float4(p2.x + bB.x, p2.y + bB.y, p3.x + bB.z, p3.y + bB.w);
        if (permute) {
            int b = m >> 10, q = m & 1023;
            int hA = colA >> 6, dA = colA & 63;
            int hB = colB >> 6, dB = colB & 63;
            *(float4*)(C + ((size_t)(b*HH + hA)*NQ + q)*DHD + dA) = vA;
            *(float4*)(C + ((size_t)(b*HH + hB)*NQ + q)*DHD + dB) = vB;
        } else {
            *(float4*)(C + (size_t)m*512 + colA) = vA;
            *(float4*)(C + (size_t)m*512 + colB) = vB;
        }
    }
}

// =====================================================================
// Kernel 2/4: Sbias[q][bh][k] = sum_d Qh[bh][q][d] * R[q][k][d]
// CTA: fixed q, k-tile 256, all 64 bh. 256 thr, 8bh x 8k per thread.
// Q duplicated in smem for f32x2 broadcast. Grid: (4, 1024).
// =====================================================================
__global__ __launch_bounds__(256, 2) void bias_gemm(
    const float* __restrict__ Qh, const float* __restrict__ R,
    float* __restrict__ Sb)
{
    extern __shared__ float sm[];
    float* Qs2 = sm;             // [d=64][132]  (64 bh duplicated + pad)
    float* Rs  = sm + 64*132;    // [d=64][260]  (256 k + pad)
    int tid = threadIdx.x;
    int q   = blockIdx.y;
    int k0  = blockIdx.x * 256;
    int kg  = tid & 31, bhg = tid >> 5;

    for (int idx = tid; idx < 64*16; idx += 256) {
        int bh = idx >> 4, d0 = (idx & 15) << 2;
        float4 v = *(const float4*)&Qh[((size_t)bh*NQ + q)*DHD + d0];
        Qs2[(d0+0)*132 + 2*bh] = v.x; Qs2[(d0+0)*132 + 2*bh+1] = v.x;
        Qs2[(d0+1)*132 + 2*bh] = v.y; Qs2[(d0+1)*132 + 2*bh+1] = v.y;
        Qs2[(d0+2)*132 + 2*bh] = v.z; Qs2[(d0+2)*132 + 2*bh+1] = v.z;
        Qs2[(d0+3)*132 + 2*bh] = v.w; Qs2[(d0+3)*132 + 2*bh+1] = v.w;
    }
    for (int idx = tid; idx < 256*16; idx += 256) {
        int kk = idx >> 4, d0 = (idx & 15) << 2;
        float4 v = *(const float4*)&R[((size_t)q*NKV + k0 + kk)*DHD + d0];
        Rs[(d0+0)*260 + kk] = v.x;
        Rs[(d0+1)*260 + kk] = v.y;
        Rs[(d0+2)*260 + kk] = v.z;
        Rs[(d0+3)*260 + kk] = v.w;
    }
    __syncthreads();

    ull acc[8][4];
#pragma unroll
    for (int i = 0; i < 8; i++)
#pragma unroll
        for (int j = 0; j < 4; j++) acc[i][j] = 0ULL;

#pragma unroll 2
    for (int d = 0; d < 64; d++) {
        ulonglong2 A0 = *(const ulonglong2*)&Qs2[d*132 + bhg*16];
        ulonglong2 A1 = *(const ulonglong2*)&Qs2[d*132 + bhg*16 + 4];
        ulonglong2 A2 = *(const ulonglong2*)&Qs2[d*132 + bhg*16 + 8];
        ulonglong2 A3 = *(const ulonglong2*)&Qs2[d*132 + bhg*16 + 12];
        ulonglong2 R0 = *(const ulonglong2*)&Rs[d*260 + kg*4];
        ulonglong2 R1 = *(const ulonglong2*)&Rs[d*260 + 128 + kg*4];
        ull av[8] = {A0.x, A0.y, A1.x, A1.y, A2.x, A2.y, A3.x, A3.y};
#pragma unroll
        for (int i = 0; i < 8; i++) {
            FMA2(acc[i][0], av[i], R0.x);
            FMA2(acc[i][1], av[i], R0.y);
            FMA2(acc[i][2], av[i], R1.x);
            FMA2(acc[i][3], av[i], R1.y);
        }
    }

#pragma unroll
    for (int i = 0; i < 8; i++) {
        int bh = bhg*8 + i;
        float* dst = Sb + ((size_t)q*BHN + bh)*NKV + k0;
        float2 p0 = unpk(acc[i][0]), p1 = unpk(acc[i][1]);
        float2 p2 = unpk(acc[i][2]), p3 = unpk(acc[i][3]);
        *(float4*)(dst + kg*4)       = make_float4(p0.x, p0.y, p1.x, p1.y);
        *(float4*)(dst + 128 + kg*4) = make_float4(p2.x, p2.y, p3.x, p3.y);
    }
}

// =====================================================================
// Kernel 3/4: fused attention. CTA per (bh, 32-q tile). 256 thr.
// Phase1: QK^T in k-chunks of 256, 4q x 8k per thread, f32x2.
// Phase2: warp softmax + attn store.
// Phase3: P@V with k-split across thread halves, f32x2 along d.
// =====================================================================
#define SROW 1028
#define QS2_OFF (32*SROW)                 // 32896
#define KS_OFF  (QS2_OFF + 64*72)         // 37504
#define MB_OFF  (KS_OFF + 64*260)         // 54144
#define ATTN_SMEM ((MB_OFF + 1024)*4)     // 220672 bytes

__global__ __launch_bounds__(256) void attn_kernel(
    const float* __restrict__ Qh, const float* __restrict__ Kh,
    const float* __restrict__ Vh, const float* __restrict__ Sb,
    const int* __restrict__ mask, float* __restrict__ attn,
    float* __restrict__ ctx)
{
    extern __shared__ float sm[];
    float* S   = sm;
    float* Qs2 = sm + QS2_OFF;   // [d=64][72] : 32 q duplicated + pad
    float* Ks  = sm + KS_OFF;    // [d=64][260]: 256 k chunk + pad
    float* mb  = sm + MB_OFF;    // [1024]
    int tid = threadIdx.x;
    int bh  = blockIdx.x;
    int q0  = blockIdx.y * 32;
    int b = bh >> 3, h = bh & 7;

    for (int idx = tid; idx < 32*16; idx += 256) {
        int qq = idx >> 4, d0 = (idx & 15) << 2;
        float4 v = *(const float4*)&Qh[((size_t)bh*NQ + q0 + qq)*DHD + d0];
        Qs2[(d0+0)*72 + 2*qq] = v.x; Qs2[(d0+0)*72 + 2*qq+1] = v.x;
        Qs2[(d0+1)*72 + 2*qq] = v.y; Qs2[(d0+1)*72 + 2*qq+1] = v.y;
        Qs2[(d0+2)*72 + 2*qq] = v.z; Qs2[(d0+2)*72 + 2*qq+1] = v.z;
        Qs2[(d0+3)*72 + 2*qq] = v.w; Qs2[(d0+3)*72 + 2*qq+1] = v.w;
    }
    for (int k = tid; k < NKV; k += 256)
        mb[k] = mask[b*NKV + k] ? 0.f : -1e30f;

    const float scale = 0.125f;
    int kg = tid & 31, qg = tid >> 5;   // qg = warp id -> Q reads broadcast

    // ---- Phase 1: QK^T + bias, 4 chunks of 256 k ----
    for (int c = 0; c < 4; c++) {
        __syncthreads();
        for (int idx = tid; idx < 256*16; idx += 256) {
            int kk = idx >> 4, d0 = (idx & 15) << 2;
            float4 v = *(const float4*)&Kh[((size_t)bh*NKV + c*256 + kk)*DHD + d0];
            Ks[(d0+0)*260 + kk] = v.x;
            Ks[(d0+1)*260 + kk] = v.y;
            Ks[(d0+2)*260 + kk] = v.z;
            Ks[(d0+3)*260 + kk] = v.w;
        }
        __syncthreads();

        ull acc[4][4];
#pragma unroll
        for (int i = 0; i < 4; i++)
#pragma unroll
            for (int j = 0; j < 4; j++) acc[i][j] = 0ULL;

#pragma unroll 4
        for (int d = 0; d < 64; d++) {
            ulonglong2 QA = *(const ulonglong2*)&Qs2[d*72 + qg*8];
            ulonglong2 QB = *(const ulonglong2*)&Qs2[d*72 + qg*8 + 4];
            ulonglong2 K0 = *(const ulonglong2*)&Ks[d*260 + kg*4];
            ulonglong2 K1 = *(const ulonglong2*)&Ks[d*260 + 128 + kg*4];
            ull av[4] = {QA.x, QA.y, QB.x, QB.y};
#pragma unroll
            for (int i = 0; i < 4; i++) {
                FMA2(acc[i][0], av[i], K0.x);
                FMA2(acc[i][1], av[i], K0.y);
                FMA2(acc[i][2], av[i], K1.x);
                FMA2(acc[i][3], av[i], K1.y);
            }
        }

        int cb = c*256;
#pragma unroll
        for (int i = 0; i < 4; i++) {
            int qq = qg*4 + i;
            const float* sbrow = Sb + ((size_t)(q0+qq)*BHN + bh)*NKV + cb;
            float4 b0 = *(const float4*)(sbrow + kg*4);
            float4 b1 = *(const float4*)(sbrow + 128 + kg*4);
            float4 m0 = *(const float4*)&mb[cb + kg*4];
            float4 m1 = *(const float4*)&mb[cb + 128 + kg*4];
            float2 p0 = unpk(acc[i][0]), p1 = unpk(acc[i][1]);
            float2 p2 = unpk(acc[i][2]), p3 = unpk(acc[i][3]);
            float4 r0, r1;
            r0.x = (p0.x + b0.x)*scale + m0.x;
            r0.y = (p0.y + b0.y)*scale + m0.y;
            r0.z = (p1.x + b0.z)*scale + m0.z;
            r0.w = (p1.y + b0.w)*scale + m0.w;
            r1.x = (p2.x + b1.x)*scale + m1.x;
            r1.y = (p2.y + b1.y)*scale + m1.y;
            r1.z = (p3.x + b1.z)*scale + m1.z;
            r1.w = (p3.y + b1.w)*scale + m1.w;
            *(float4*)&S[qq*SROW + cb + kg*4]       = r0;
            *(float4*)&S[qq*SROW + cb + 128 + kg*4] = r1;
        }
    }
    __syncthreads();

    // ---- Phase 2: softmax + attn store ----
    int lane = tid & 31, wid = tid >> 5;
    for (int r = 0; r < 4; r++) {
        float* row = S + (wid*4 + r)*SROW;
        float m = -3.4e38f;
        for (int k = lane; k < NKV; k += 32) m = fmaxf(m, row[k]);
#pragma unroll
        for (int o = 16; o; o >>= 1) m = fmaxf(m, __shfl_xor_sync(0xffffffffu, m, o));
        float s = 0.f;
        for (int k = lane; k < NKV; k += 32) {
            float e = __expf(row[k] - m);
            row[k] = e; s += e;
        }
#pragma unroll
        for (int o = 16; o; o >>= 1) s += __shfl_xor_sync(0xffffffffu, s, o);
        float inv = 1.f / s;
        __syncwarp();
        float* arow = attn + ((size_t)bh*NQ + q0 + wid*4 + r)*NKV;
        for (int k = lane*4; k < NKV; k += 128) {
            float4 v = *(float4*)&row[k];
            v.x *= inv; v.y *= inv; v.z *= inv; v.w *= inv;
            *(float4*)&row[k] = v;
            *(float4*)&arow[k] = v;
        }
        __syncwarp();
    }
    __syncthreads();

    // ---- Phase 3: ctx = P @ V, k-split in half ----
    int half = tid >> 7;          // 0: k[0..511], 1: k[512..1023]
    int t    = tid & 127;
    int qg2  = t >> 4;            // 8 groups x 4 q
    int dg   = t & 15;            // 16 groups x 4 d
    float* Vs = Ks + half * (64*68);    // [64][68] per half

    ull acc[4][2];
#pragma unroll
    for (int i = 0; i < 4; i++) { acc[i][0] = 0ULL; acc[i][1] = 0ULL; }

    for (int kb = 0; kb < 8; kb++) {
        int koff = half*512 + kb*64;
        for (int r = 0; r < 8; r++) {
            int idx = t + r*128;
            int kk = idx >> 4, d0 = (idx & 15) << 2;
            *(float4*)&Vs[kk*68 + d0] =
                *(const float4*)&Vh[((size_t)bh*NKV + koff + kk)*DHD + d0];
        }
        __syncthreads();
#pragma unroll 2
        for (int kk4 = 0; kk4 < 16; kk4++) {
            float4 p[4];
#pragma unroll
            for (int i = 0; i < 4; i++)
                p[i] = *(float4*)&S[(qg2*4 + i)*SROW + koff + kk4*4];
#pragma unroll
            for (int tt = 0; tt < 3+1; tt++) {
                ulonglong2 v = *(const ulonglong2*)&Vs[(kk4*4 + tt)*68 + dg*4];
                float pv[4] = { tt==0?p[0].x: tt==1?p[0].y: tt==2?p[0].z:p[0].w,
                                tt==0?p[1].x: tt==1?p[1].y: tt==2?p[1].z:p[1].w,
                                tt==0?p[2].x: tt==1?p[2].y: tt==2?p[2].z:p[2].w,
                                tt==0?p[3].x: tt==1?p[3].y: tt==2?p[3].z:p[3].w };
#pragma unroll
                for (int i = 0; i < 4; i++) {
                    ull pd = dup2(pv[i]);
                    FMA2(acc[i][0], pd, v.x);
                    FMA2(acc[i][1], pd, v.y);
                }
            }
        }
        __syncthreads();
    }

    float* scr = Qs2;   // reuse as 32x64 scratch
    if (half == 1) {
#pragma unroll
        for (int i = 0; i < 4; i++) {
            float2 a = unpk(acc[i][0]), c2 = unpk(acc[i][1]);
            *(float4*)&scr[(qg2*4 + i)*64 + dg*4] = make_float4(a.x, a.y, c2.x, c2.y);
        }
    }
    __syncthreads();
    if (half == 0) {
#pragma unroll
        for (int i = 0; i < 4; i++) {
            int qq = qg2*4 + i;
            float4 o = *(float4*)&scr[qq*64 + dg*4];
            float2 a = unpk(acc[i][0]), c2 = unpk(acc[i][1]);
            o.x += a.x; o.y += a.y; o.z += c2.x; o.w += c2.y;
            *(float4*)(ctx + ((size_t)b*NQ + q0 + qq)*DM + h*DHD + dg*4) = o;
        }
    }
}

// =====================================================================
// launcher
// =====================================================================
extern "C" void kernel_launch(void* const* d_in, const int* in_sizes, int n_in,
                              void* d_out, int out_size)
{
    const float* q    = (const float*)d_in[0];
    const float* kv   = (const float*)d_in[1];
    const int*   mask = (const int*)  d_in[2];
    const float* Wq   = (const float*)d_in[3];
    const float* bq   = (const float*)d_in[4];
    const float* Wk   = (const float*)d_in[5];
    const float* bk   = (const float*)d_in[6];
    const float* Wv   = (const float*)d_in[7];
    const float* bv   = (const float*)d_in[8];
    const float* Wo   = (const float*)d_in[9];
    const float* bo   = (const float*)d_in[10];
    const float* R    = (const float*)d_in[11];

    float* out = (float*)d_out;
    const size_t out_elems  = (size_t)BB*NQ*DM;
    const size_t attn_elems = (size_t)BHN*NQ*NKV;

    float *Qh, *Kh, *Vh, *Sb, *ctx, *attn_fb;
    cudaGetSymbolAddress((void**)&Qh,  g_Qh);
    cudaGetSymbolAddress((void**)&Kh,  g_Kh);
    cudaGetSymbolAddress((void**)&Vh,  g_Vh);
    cudaGetSymbolAddress((void**)&Sb,  g_Sb);
    cudaGetSymbolAddress((void**)&ctx, g_ctx);
    cudaGetSymbolAddress((void**)&attn_fb, g_attn_fallback);

    float* attn = ((size_t)out_size >= out_elems + attn_elems)
                ? (out + out_elems) : attn_fb;

    const int biasSmem = (64*132 + 64*260) * 4;   // 100352
    cudaFuncSetAttribute(bias_gemm, cudaFuncAttributeMaxDynamicSharedMemorySize, biasSmem);
    cudaFuncSetAttribute(attn_kernel, cudaFuncAttributeMaxDynamicSharedMemorySize, ATTN_SMEM);

    dim3 gProj(4, 64);
    proj_gemm<<<gProj, 256>>>(q,  Wq, bq, Qh, 1);
    proj_gemm<<<gProj, 256>>>(kv, Wk, bk, Kh, 1);
    proj_gemm<<<gProj, 256>>>(kv, Wv, bv, Vh, 1);

    bias_gemm<<<dim3(4, 1024), 256, biasSmem>>>(Qh, R, Sb);

    attn_kernel<<<dim3(64, 32), 256, ATTN_SMEM>>>(Qh, Kh, Vh, Sb, mask, attn, ctx);

    proj_gemm<<<gProj, 256>>>(ctx, Wo, bo, out, 0);
}

// round 4
// speedup vs baseline: 1.0071x; 1.0071x over previous
#include <cuda_runtime.h>
#include <cstdint>
#include <cstddef>

#define BB    8
#define HH    8
#define NQ    1024
#define NKV   1024
#define DHD   64
#define DM    512
#define BHN   (BB*HH)   // 64

typedef unsigned long long ull;

// packed f32x2 FMA: c = a*b + c  (sm_103a FFMA2)
#define FMA2(c,a,b) asm("fma.rn.f32x2 %0, %1, %2, %0;" : "+l"(c) : "l"(a), "l"(b))

__device__ __forceinline__ ull dup2(float x) {
    ull r; unsigned u = __float_as_uint(x);
    asm("mov.b64 %0, {%1, %1};" : "=l"(r) : "r"(u));
    return r;
}
__device__ __forceinline__ float2 unpk(ull v) {
    unsigned lo, hi;
    asm("mov.b64 {%0, %1}, %2;" : "=r"(lo), "=r"(hi) : "l"(v));
    return make_float2(__uint_as_float(lo), __uint_as_float(hi));
}

// ---------------- device scratch ----------------
__device__ float g_Qh[(size_t)BHN*NQ*DHD];
__device__ float g_Kh[(size_t)BHN*NKV*DHD];
__device__ float g_Vh[(size_t)BHN*NKV*DHD];
__device__ float g_Sb[(size_t)NQ*BHN*NKV];
__device__ float g_ctx[(size_t)BB*NQ*DM];
__device__ float g_attn_fallback[(size_t)BHN*NQ*NKV];

// =====================================================================
// Kernel 1/4: C[M,512] = A[M,512] @ W[512,512] + bias (f32x2 core)
// 128x128 tile, BK=8, 256 thr, 8 rows x 8 cols per thread (cols split
// as {nc*4..+3} and {64+nc*4..+3} for conflict-free LDS).
// =====================================================================
__global__ __launch_bounds__(256) void proj_gemm(
    const float* __restrict__ A, const float* __restrict__ W,
    const float* __restrict__ bias, float* __restrict__ C, int permute)
{
    const int K = 512, N = 512;
    __shared__ float As2[8][260];   // a-rows duplicated: [k][2*row]
    __shared__ float Ws[8][128];
    int tid  = threadIdx.x;
    int cRow = blockIdx.y, cCol = blockIdx.x;
    int aRow = tid >> 1;            // 0..127
    int aCol = (tid & 1) << 2;      // 0 or 4
    int wRow = tid >> 5;            // 0..7
    int wCol = (tid & 31) << 2;     // 0..124
    int tRow = (tid >> 4) << 3;     // 0..120
    int nc   = tid & 15;            // 0..15

    const float* Ap = A + (size_t)(cRow*128 + aRow)*K + aCol;
    const float* Wp = W + (size_t)wRow*N + cCol*128 + wCol;

    ull acc[8][4];
#pragma unroll
    for (int i = 0; i < 8; i++)
#pragma unroll
        for (int j = 0; j < 4; j++) acc[i][j] = 0ULL;

    for (int kb = 0; kb < K; kb += 8) {
        float4 a4 = *(const float4*)(Ap + kb);
        As2[aCol+0][aRow*2] = a4.x; As2[aCol+0][aRow*2+1] = a4.x;
        As2[aCol+1][aRow*2] = a4.y; As2[aCol+1][aRow*2+1] = a4.y;
        As2[aCol+2][aRow*2] = a4.z; As2[aCol+2][aRow*2+1] = a4.z;
        As2[aCol+3][aRow*2] = a4.w; As2[aCol+3][aRow*2+1] = a4.w;
        *(float4*)&Ws[wRow][wCol] = *(const float4*)(Wp + (size_t)kb*N);
        __syncthreads();
#pragma unroll
        for (int kk = 0; kk < 8; kk++) {
            ulonglong2 A0 = *(const ulonglong2*)&As2[kk][tRow*2];
            ulonglong2 A1 = *(const ulonglong2*)&As2[kk][tRow*2 + 4];
            ulonglong2 A2 = *(const ulonglong2*)&As2[kk][tRow*2 + 8];
            ulonglong2 A3 = *(const ulonglong2*)&As2[kk][tRow*2 + 12];
            ulonglong2 B0 = *(const ulonglong2*)&Ws[kk][nc*4];
            ulonglong2 B1 = *(const ulonglong2*)&Ws[kk][64 + nc*4];
            ull av[8] = {A0.x, A0.y, A1.x, A1.y, A2.x, A2.y, A3.x, A3.y};
#pragma unroll
            for (int i = 0; i < 8; i++) {
                FMA2(acc[i][0], av[i], B0.x);
                FMA2(acc[i][1], av[i], B0.y);
                FMA2(acc[i][2], av[i], B1.x);
                FMA2(acc[i][3], av[i], B1.y);
            }
        }
        __syncthreads();
    }

    int colA = cCol*128 + nc*4;
    int colB = colA + 64;
    float4 bA = *(const float4*)&bias[colA];
    float4 bB = *(const float4*)&bias[colB];

#pragma unroll
    for (int i = 0; i < 8; i++) {
        int m = cRow*128 + tRow + i;
        float2 p0 = unpk(acc[i][0]), p1 = unpk(acc[i][1]);
        float2 p2 = unpk(acc[i][2]), p3 = unpk(acc[i][3]);
        float4 vA = make_float4(p0.x + bA.x, p0.y + bA.y, p1.x + bA.z, p1.y + bA.w);
        float4 vB = make_float4(p2.x + bB.x, p2.y + bB.y, p3.x + bB.z, p3.y + bB.w);
        if (permute) {
            int b = m >> 10, q = m & 1023;
            int hA = colA >> 6, dA = colA & 63;
            int hB = colB >> 6, dB = colB & 63;
            *(float4*)(C + ((size_t)(b*HH + hA)*NQ + q)*DHD + dA) = vA;
            *(float4*)(C + ((size_t)(b*HH + hB)*NQ + q)*DHD + dB) = vB;
        } else {
            *(float4*)(C + (size_t)m*512 + colA) = vA;
            *(float4*)(C + (size_t)m*512 + colB) = vB;
        }
    }
}

// =====================================================================
// Kernel 2/4: Sbias[q][bh][k] = sum_d Qh[bh][q][d] * R[q][k][d]
// CTA: fixed q, k-tile 256, all 64 bh. 256 thr, 8bh x 8k per thread.
// Q duplicated in smem for f32x2 broadcast. Grid: (4, 1024).
// =====================================================================
__global__ __launch_bounds__(256, 2) void bias_gemm(
    const float* __restrict__ Qh, const float* __restrict__ R,
    float* __restrict__ Sb)
{
    extern __shared__ float sm[];
    float* Qs2 = sm;             // [d=64][132]  (64 bh duplicated + pad)
    float* Rs  = sm + 64*132;    // [d=64][260]  (256 k + pad)
    int tid = threadIdx.x;
    int q   = blockIdx.y;
    int k0  = blockIdx.x * 256;
    int kg  = tid & 31, bhg = tid >> 5;

    for (int idx = tid; idx < 64*16; idx += 256) {
        int bh = idx >> 4, d0 = (idx & 15) << 2;
        float4 v = *(const float4*)&Qh[((size_t)bh*NQ + q)*DHD + d0];
        Qs2[(d0+0)*132 + 2*bh] = v.x; Qs2[(d0+0)*132 + 2*bh+1] = v.x;
        Qs2[(d0+1)*132 + 2*bh] = v.y; Qs2[(d0+1)*132 + 2*bh+1] = v.y;
        Qs2[(d0+2)*132 + 2*bh] = v.z; Qs2[(d0+2)*132 + 2*bh+1] = v.z;
        Qs2[(d0+3)*132 + 2*bh] = v.w; Qs2[(d0+3)*132 + 2*bh+1] = v.w;
    }
    for (int idx = tid; idx < 256*16; idx += 256) {
        int kk = idx >> 4, d0 = (idx & 15) << 2;
        float4 v = *(const float4*)&R[((size_t)q*NKV + k0 + kk)*DHD + d0];
        Rs[(d0+0)*260 + kk] = v.x;
        Rs[(d0+1)*260 + kk] = v.y;
        Rs[(d0+2)*260 + kk] = v.z;
        Rs[(d0+3)*260 + kk] = v.w;
    }
    __syncthreads();

    ull acc[8][4];
#pragma unroll
    for (int i = 0; i < 8; i++)
#pragma unroll
        for (int j = 0; j < 4; j++) acc[i][j] = 0ULL;

#pragma unroll 2
    for (int d = 0; d < 64; d++) {
        ulonglong2 A0 = *(const ulonglong2*)&Qs2[d*132 + bhg*16];
        ulonglong2 A1 = *(const ulonglong2*)&Qs2[d*132 + bhg*16 + 4];
        ulonglong2 A2 = *(const ulonglong2*)&Qs2[d*132 + bhg*16 + 8];
        ulonglong2 A3 = *(const ulonglong2*)&Qs2[d*132 + bhg*16 + 12];
        ulonglong2 R0 = *(const ulonglong2*)&Rs[d*260 + kg*4];
        ulonglong2 R1 = *(const ulonglong2*)&Rs[d*260 + 128 + kg*4];
        ull av[8] = {A0.x, A0.y, A1.x, A1.y, A2.x, A2.y, A3.x, A3.y};
#pragma unroll
        for (int i = 0; i < 8; i++) {
            FMA2(acc[i][0], av[i], R0.x);
            FMA2(acc[i][1], av[i], R0.y);
            FMA2(acc[i][2], av[i], R1.x);
            FMA2(acc[i][3], av[i], R1.y);
        }
    }

#pragma unroll
    for (int i = 0; i < 8; i++) {
        int bh = bhg*8 + i;
        float* dst = Sb + ((size_t)q*BHN + bh)*NKV + k0;
        float2 p0 = unpk(acc[i][0]), p1 = unpk(acc[i][1]);
        float2 p2 = unpk(acc[i][2]), p3 = unpk(acc[i][3]);
        *(float4*)(dst + kg*4)       = make_float4(p0.x, p0.y, p1.x, p1.y);
        *(float4*)(dst + 128 + kg*4) = make_float4(p2.x, p2.y, p3.x, p3.y);
    }
}

// =====================================================================
// Kernel 3/4: fused attention. CTA per (bh, 32-q tile). 256 thr.
// Phase1: QK^T in k-chunks of 256, 4q x 8k per thread, f32x2.
// Phase2: warp softmax + attn store.
// Phase3: P@V with k-split across thread halves, f32x2 along d.
// =====================================================================
#define SROW 1028
#define QS2_OFF (32*SROW)                 // 32896
#define KS_OFF  (QS2_OFF + 64*72)         // 37504
#define MB_OFF  (KS_OFF + 64*260)         // 54144
#define ATTN_SMEM ((MB_OFF + 1024)*4)     // 220672 bytes

__global__ __launch_bounds__(256) void attn_kernel(
    const float* __restrict__ Qh, const float* __restrict__ Kh,
    const float* __restrict__ Vh, const float* __restrict__ Sb,
    const int* __restrict__ mask, float* __restrict__ attn,
    float* __restrict__ ctx)
{
    extern __shared__ float sm[];
    float* S   = sm;
    float* Qs2 = sm + QS2_OFF;   // [d=64][72] : 32 q duplicated + pad
    float* Ks  = sm + KS_OFF;    // [d=64][260]: 256 k chunk + pad
    float* mb  = sm + MB_OFF;    // [1024]
    int tid = threadIdx.x;
    int bh  = blockIdx.x;
    int q0  = blockIdx.y * 32;
    int b = bh >> 3, h = bh & 7;

    for (int idx = tid; idx < 32*16; idx += 256) {
        int qq = idx >> 4, d0 = (idx & 15) << 2;
        float4 v = *(const float4*)&Qh[((size_t)bh*NQ + q0 + qq)*DHD + d0];
        Qs2[(d0+0)*72 + 2*qq] = v.x; Qs2[(d0+0)*72 + 2*qq+1] = v.x;
        Qs2[(d0+1)*72 + 2*qq] = v.y; Qs2[(d0+1)*72 + 2*qq+1] = v.y;
        Qs2[(d0+2)*72 + 2*qq] = v.z; Qs2[(d0+2)*72 + 2*qq+1] = v.z;
        Qs2[(d0+3)*72 + 2*qq] = v.w; Qs2[(d0+3)*72 + 2*qq+1] = v.w;
    }
    for (int k = tid; k < NKV; k += 256)
        mb[k] = mask[b*NKV + k] ? 0.f : -1e30f;

    const float scale = 0.125f;
    int kg = tid & 31, qg = tid >> 5;   // qg = warp id -> Q reads broadcast

    // ---- Phase 1: QK^T + bias, 4 chunks of 256 k ----
    for (int c = 0; c < 4; c++) {
        __syncthreads();
        for (int idx = tid; idx < 256*16; idx += 256) {
            int kk = idx >> 4, d0 = (idx & 15) << 2;
            float4 v = *(const float4*)&Kh[((size_t)bh*NKV + c*256 + kk)*DHD + d0];
            Ks[(d0+0)*260 + kk] = v.x;
            Ks[(d0+1)*260 + kk] = v.y;
            Ks[(d0+2)*260 + kk] = v.z;
            Ks[(d0+3)*260 + kk] = v.w;
        }
        __syncthreads();

        ull acc[4][4];
#pragma unroll
        for (int i = 0; i < 4; i++)
#pragma unroll
            for (int j = 0; j < 4; j++) acc[i][j] = 0ULL;

#pragma unroll 4
        for (int d = 0; d < 64; d++) {
            ulonglong2 QA = *(const ulonglong2*)&Qs2[d*72 + qg*8];
            ulonglong2 QB = *(const ulonglong2*)&Qs2[d*72 + qg*8 + 4];
            ulonglong2 K0 = *(const ulonglong2*)&Ks[d*260 + kg*4];
            ulonglong2 K1 = *(const ulonglong2*)&Ks[d*260 + 128 + kg*4];
            ull av[4] = {QA.x, QA.y, QB.x, QB.y};
#pragma unroll
            for (int i = 0; i < 4; i++) {
                FMA2(acc[i][0], av[i], K0.x);
                FMA2(acc[i][1], av[i], K0.y);
                FMA2(acc[i][2], av[i], K1.x);
                FMA2(acc[i][3], av[i], K1.y);
            }
        }

        int cb = c*256;
#pragma unroll
        for (int i = 0; i < 4; i++) {
            int qq = qg*4 + i;
            const float* sbrow = Sb + ((size_t)(q0+qq)*BHN + bh)*NKV + cb;
            float4 b0 = *(const float4*)(sbrow + kg*4);
            float4 b1 = *(const float4*)(sbrow + 128 + kg*4);
            float4 m0 = *(const float4*)&mb[cb + kg*4];
            float4 m1 = *(const float4*)&mb[cb + 128 + kg*4];
            float2 p0 = unpk(acc[i][0]), p1 = unpk(acc[i][1]);
            float2 p2 = unpk(acc[i][2]), p3 = unpk(acc[i][3]);
            float4 r0, r1;
            r0.x = (p0.x + b0.x)*scale + m0.x;
            r0.y = (p0.y + b0.y)*scale + m0.y;
            r0.z = (p1.x + b0.z)*scale + m0.z;
            r0.w = (p1.y + b0.w)*scale + m0.w;
            r1.x = (p2.x + b1.x)*scale + m1.x;
            r1.y = (p2.y + b1.y)*scale + m1.y;
            r1.z = (p3.x + b1.z)*scale + m1.z;
            r1.w = (p3.y + b1.w)*scale + m1.w;
            *(float4*)&S[qq*SROW + cb + kg*4]       = r0;
            *(float4*)&S[qq*SROW + cb + 128 + kg*4] = r1;
        }
    }
    __syncthreads();

    // ---- Phase 2: softmax + attn store ----
    int lane = tid & 31, wid = tid >> 5;
    for (int r = 0; r < 4; r++) {
        float* row = S + (wid*4 + r)*SROW;
        float m = -3.4e38f;
        for (int k = lane; k < NKV; k += 32) m = fmaxf(m, row[k]);
#pragma unroll
        for (int o = 16; o; o >>= 1) m = fmaxf(m, __shfl_xor_sync(0xffffffffu, m, o));
        float s = 0.f;
        for (int k = lane; k < NKV; k += 32) {
            float e = __expf(row[k] - m);
            row[k] = e; s += e;
        }
#pragma unroll
        for (int o = 16; o; o >>= 1) s += __shfl_xor_sync(0xffffffffu, s, o);
        float inv = 1.f / s;
        __syncwarp();
        float* arow = attn + ((size_t)bh*NQ + q0 + wid*4 + r)*NKV;
        for (int k = lane*4; k < NKV; k += 128) {
            float4 v = *(float4*)&row[k];
            v.x *= inv; v.y *= inv; v.z *= inv; v.w *= inv;
            *(float4*)&row[k] = v;
            *(float4*)&arow[k] = v;
        }
        __syncwarp();
    }
    __syncthreads();

    // ---- Phase 3: ctx = P @ V, k-split in half ----
    int half = tid >> 7;          // 0: k[0..511], 1: k[512..1023]
    int t    = tid & 127;
    int qg2  = t >> 4;            // 8 groups x 4 q
    int dg   = t & 15;            // 16 groups x 4 d
    float* Vs = Ks + half * (64*68);    // [64][68] per half

    ull acc[4][2];
#pragma unroll
    for (int i = 0; i < 4; i++) { acc[i][0] = 0ULL; acc[i][1] = 0ULL; }

    for (int kb = 0; kb < 8; kb++) {
        int koff = half*512 + kb*64;
        for (int r = 0; r < 8; r++) {
            int idx = t + r*128;
            int kk = idx >> 4, d0 = (idx & 15) << 2;
            *(float4*)&Vs[kk*68 + d0] =
                *(const float4*)&Vh[((size_t)bh*NKV + koff + kk)*DHD + d0];
        }
        __syncthreads();
#pragma unroll 2
        for (int kk4 = 0; kk4 < 16; kk4++) {
            float4 p[4];
#pragma unroll
            for (int i = 0; i < 4; i++)
                p[i] = *(float4*)&S[(qg2*4 + i)*SROW + koff + kk4*4];
#pragma unroll
            for (int tt = 0; tt < 3+1; tt++) {
                ulonglong2 v = *(const ulonglong2*)&Vs[(kk4*4 + tt)*68 + dg*4];
                float pv[4] = { tt==0?p[0].x: tt==1?p[0].y: tt==2?p[0].z:p[0].w,
                                tt==0?p[1].x: tt==1?p[1].y: tt==2?p[1].z:p[1].w,
                                tt==0?p[2].x: tt==1?p[2].y: tt==2?p[2].z:p[2].w,
                                tt==0?p[3].x: tt==1?p[3].y: tt==2?p[3].z:p[3].w };
#pragma unroll
                for (int i = 0; i < 4; i++) {
                    ull pd = dup2(pv[i]);
                    FMA2(acc[i][0], pd, v.x);
                    FMA2(acc[i][1], pd, v.y);
                }
            }
        }
        __syncthreads();
    }

    float* scr = Qs2;   // reuse as 32x64 scratch
    if (half == 1) {
#pragma unroll
        for (int i = 0; i < 4; i++) {
            float2 a = unpk(acc[i][0]), c2 = unpk(acc[i][1]);
            *(float4*)&scr[(qg2*4 + i)*64 + dg*4] = make_float4(a.x, a.y, c2.x, c2.y);
        }
    }
    __syncthreads();
    if (half == 0) {
#pragma unroll
        for (int i = 0; i < 4; i++) {
            int qq = qg2*4 + i;
            float4 o = *(float4*)&scr[qq*64 + dg*4];
            float2 a = unpk(acc[i][0]), c2 = unpk(acc[i][1]);
            o.x += a.x; o.y += a.y; o.z += c2.x; o.w += c2.y;
            *(float4*)(ctx + ((size_t)b*NQ + q0 + qq)*DM + h*DHD + dg*4) = o;
        }
    }
}

// =====================================================================
// launcher
// =====================================================================
extern "C" void kernel_launch(void* const* d_in, const int* in_sizes, int n_in,
                              void* d_out, int out_size)
{
    const float* q    = (const float*)d_in[0];
    const float* kv   = (const float*)d_in[1];
    const int*   mask = (const int*)  d_in[2];
    const float* Wq   = (const float*)d_in[3];
    const float* bq   = (const float*)d_in[4];
    const float* Wk   = (const float*)d_in[5];
    const float* bk   = (const float*)d_in[6];
    const float* Wv   = (const float*)d_in[7];
    const float* bv   = (const float*)d_in[8];
    const float* Wo   = (const float*)d_in[9];
    const float* bo   = (const float*)d_in[10];
    const float* R    = (const float*)d_in[11];

    float* out = (float*)d_out;
    const size_t out_elems  = (size_t)BB*NQ*DM;
    const size_t attn_elems = (size_t)BHN*NQ*NKV;

    float *Qh, *Kh, *Vh, *Sb, *ctx, *attn_fb;
    cudaGetSymbolAddress((void**)&Qh,  g_Qh);
    cudaGetSymbolAddress((void**)&Kh,  g_Kh);
    cudaGetSymbolAddress((void**)&Vh,  g_Vh);
    cudaGetSymbolAddress((void**)&Sb,  g_Sb);
    cudaGetSymbolAddress((void**)&ctx, g_ctx);
    cudaGetSymbolAddress((void**)&attn_fb, g_attn_fallback);

    float* attn = ((size_t)out_size >= out_elems + attn_elems)
                ? (out + out_elems) : attn_fb;

    const int biasSmem = (64*132 + 64*260) * 4;   // 100352
    cudaFuncSetAttribute(bias_gemm, cudaFuncAttributeMaxDynamicSharedMemorySize, biasSmem);
    cudaFuncSetAttribute(attn_kernel, cudaFuncAttributeMaxDynamicSharedMemorySize, ATTN_SMEM);

    dim3 gProj(4, 64);
    proj_gemm<<<gProj, 256>>>(q,  Wq, bq, Qh, 1);
    proj_gemm<<<gProj, 256>>>(kv, Wk, bk, Kh, 1);
    proj_gemm<<<gProj, 256>>>(kv, Wv, bv, Vh, 1);

    bias_gemm<<<dim3(4, 1024), 256, biasSmem>>>(Qh, R, Sb);

    attn_kernel<<<dim3(64, 32), 256, ATTN_SMEM>>>(Qh, Kh, Vh, Sb, mask, attn, ctx);

    proj_gemm<<<gProj, 256>>>(ctx, Wo, bo, out, 0);
}

// round 6
// speedup vs baseline: 1.2797x; 1.2707x over previous
#include <cuda_runtime.h>
#include <cuda_bf16.h>
#include <cstdint>
#include <cstddef>

#define BB    8
#define HH    8
#define NQ    1024
#define NKV   1024
#define DHD   64
#define DM    512
#define BHN   (BB*HH)

typedef unsigned long long ull;
typedef uint32_t u32;

#define FMA2(c,a,b) asm("fma.rn.f32x2 %0, %1, %2, %0;" : "+l"(c) : "l"(a), "l"(b))
__device__ __forceinline__ ull dup2(float x) {
    ull r; unsigned u = __float_as_uint(x);
    asm("mov.b64 %0, {%1, %1};" : "=l"(r) : "r"(u));
    return r;
}
__device__ __forceinline__ float2 unpk(ull v) {
    unsigned lo, hi;
    asm("mov.b64 {%0, %1}, %2;" : "=r"(lo), "=r"(hi) : "l"(v));
    return make_float2(__uint_as_float(lo), __uint_as_float(hi));
}

__device__ __forceinline__ u32 smem_u32(const void* p) {
    u32 a;
    asm("{ .reg .u64 t; cvta.to.shared.u64 t, %1; cvt.u32.u64 %0, t; }" : "=r"(a) : "l"(p));
    return a;
}
__device__ __forceinline__ void ldm_x4(u32* r, u32 a) {
    asm volatile("ldmatrix.sync.aligned.m8n8.x4.shared.b16 {%0,%1,%2,%3}, [%4];"
        : "=r"(r[0]),"=r"(r[1]),"=r"(r[2]),"=r"(r[3]) : "r"(a));
}
__device__ __forceinline__ void ldm_x4t(u32* r, u32 a) {
    asm volatile("ldmatrix.sync.aligned.m8n8.x4.trans.shared.b16 {%0,%1,%2,%3}, [%4];"
        : "=r"(r[0]),"=r"(r[1]),"=r"(r[2]),"=r"(r[3]) : "r"(a));
}
__device__ __forceinline__ void mma_bf16(float* c, const u32* a, u32 b0, u32 b1) {
    asm volatile("mma.sync.aligned.m16n8k16.row.col.f32.bf16.bf16.f32 "
        "{%0,%1,%2,%3}, {%4,%5,%6,%7}, {%8,%9}, {%0,%1,%2,%3};"
        : "+f"(c[0]),"+f"(c[1]),"+f"(c[2]),"+f"(c[3])
        : "r"(a[0]),"r"(a[1]),"r"(a[2]),"r"(a[3]), "r"(b0),"r"(b1));
}
__device__ __forceinline__ void split4(float4 v, ull& hi8, ull& lo8) {
    __nv_bfloat162 h01 = __floats2bfloat162_rn(v.x, v.y);
    __nv_bfloat162 h23 = __floats2bfloat162_rn(v.z, v.w);
    float2 f01 = __bfloat1622float2(h01);
    float2 f23 = __bfloat1622float2(h23);
    __nv_bfloat162 l01 = __floats2bfloat162_rn(v.x - f01.x, v.y - f01.y);
    __nv_bfloat162 l23 = __floats2bfloat162_rn(v.z - f23.x, v.w - f23.y);
    u32 uh0 = *(u32*)&h01, uh1 = *(u32*)&h23;
    u32 ul0 = *(u32*)&l01, ul1 = *(u32*)&l23;
    hi8 = (ull)uh0 | ((ull)uh1 << 32);
    lo8 = (ull)ul0 | ((ull)ul1 << 32);
}

// ---------------- device scratch ----------------
__device__ float g_Qh[(size_t)BHN*NQ*DHD];
__device__ float g_Kh[(size_t)BHN*NKV*DHD];
__device__ float g_Vh[(size_t)BHN*NKV*DHD];
__device__ float g_Sb[(size_t)NQ*BHN*NKV];
__device__ float g_ctx[(size_t)BB*NQ*DM];
__device__ float g_attn_fallback[(size_t)BHN*NQ*NKV];

// =====================================================================
// proj_mma: C[8192x512] = A @ W + bias, bf16 mma 3-split.
// 128x128 tile, K-chunks of 32, 8 warps (4m x 2n), warp tile 32x64.
// A smem [128][40] bf16 (hi/lo), W smem [32][136] bf16 (hi/lo).
// =====================================================================
#define PJ_AH 0
#define PJ_AL 10240
#define PJ_WH 20480
#define PJ_WL 29184
#define PROJ_SMEM 37888

__global__ __launch_bounds__(256) void proj_mma(
    const float* __restrict__ A, const float* __restrict__ W,
    const float* __restrict__ bias, float* __restrict__ C, int permute)
{
    extern __shared__ __align__(128) char smem[];
    u32 sb = smem_u32(smem);
    int tid = threadIdx.x, wid = tid >> 5, lane = tid & 31;
    int m0 = blockIdx.y * 128, n0 = blockIdx.x * 128;
    int wm = wid & 3, wn = wid >> 2;

    float acc[2][8][4];
#pragma unroll
    for (int m = 0; m < 2; m++)
#pragma unroll
        for (int j = 0; j < 8; j++)
#pragma unroll
            for (int t = 0; t < 4; t++) acc[m][j][t] = 0.f;

    float4 pa[4], pw[4];
#pragma unroll
    for (int r = 0; r < 4; r++) {
        int idx = tid + r * 256;
        pa[r] = *(const float4*)(A + (size_t)(m0 + (idx >> 3)) * 512 + ((idx & 7) << 2));
        pw[r] = *(const float4*)(W + (size_t)(idx >> 5) * 512 + n0 + ((idx & 31) << 2));
    }

    for (int kb = 0; kb < 16; kb++) {
        if (kb) __syncthreads();
#pragma unroll
        for (int r = 0; r < 4; r++) {
            int idx = tid + r * 256;
            {
                int row = idx >> 3, col = (idx & 7) << 2;
                ull h8, l8; split4(pa[r], h8, l8);
                *(ull*)(smem + PJ_AH + (row * 40 + col) * 2) = h8;
                *(ull*)(smem + PJ_AL + (row * 40 + col) * 2) = l8;
            }
            {
                int row = idx >> 5, col = (idx & 31) << 2;
                ull h8, l8; split4(pw[r], h8, l8);
                *(ull*)(smem + PJ_WH + (row * 136 + col) * 2) = h8;
                *(ull*)(smem + PJ_WL + (row * 136 + col) * 2) = l8;
            }
        }
        __syncthreads();
        if (kb < 15) {
            int k0 = (kb + 1) * 32;
#pragma unroll
            for (int r = 0; r < 4; r++) {
                int idx = tid + r * 256;
                pa[r] = *(const float4*)(A + (size_t)(m0 + (idx >> 3)) * 512 + k0 + ((idx & 7) << 2));
                pw[r] = *(const float4*)(W + (size_t)(k0 + (idx >> 5)) * 512 + n0 + ((idx & 31) << 2));
            }
        }
#pragma unroll
        for (int ks = 0; ks < 32; ks += 16) {
            u32 ah[2][4], al[2][4];
#pragma unroll
            for (int f = 0; f < 2; f++) {
                u32 ra = (u32)((wm * 32 + f * 16 + (lane & 15)) * 40 + ks + ((lane >> 4) << 3)) * 2;
                ldm_x4(ah[f], sb + PJ_AH + ra);
                ldm_x4(al[f], sb + PJ_AL + ra);
            }
#pragma unroll
            for (int nf = 0; nf < 4; nf++) {
                u32 rb = (u32)((ks + (lane & 15)) * 136 + wn * 64 + nf * 16 + ((lane >> 4) << 3)) * 2;
                u32 bh4[4], bl4[4];
                ldm_x4t(bh4, sb + PJ_WH + rb);
                ldm_x4t(bl4, sb + PJ_WL + rb);
#pragma unroll
                for (int m = 0; m < 2; m++) {
                    mma_bf16(acc[m][nf*2],   ah[m], bh4[0], bh4[1]);
                    mma_bf16(acc[m][nf*2],   ah[m], bl4[0], bl4[1]);
                    mma_bf16(acc[m][nf*2],   al[m], bh4[0], bh4[1]);
                    mma_bf16(acc[m][nf*2+1], ah[m], bh4[2], bh4[3]);
                    mma_bf16(acc[m][nf*2+1], ah[m], bl4[2], bl4[3]);
                    mma_bf16(acc[m][nf*2+1], al[m], bh4[2], bh4[3]);
                }
            }
        }
    }

    int r0 = m0 + wm * 32 + (lane >> 2);
    int cb = n0 + wn * 64 + (lane & 3) * 2;
#pragma unroll
    for (int m = 0; m < 2; m++) {
#pragma unroll
        for (int j = 0; j < 8; j++) {
            int col = cb + j * 8;
            float2 bv = *(const float2*)&bias[col];
            int rowA = r0 + m * 16, rowB = rowA + 8;
            float2 vA = make_float2(acc[m][j][0] + bv.x, acc[m][j][1] + bv.y);
            float2 vB = make_float2(acc[m][j][2] + bv.x, acc[m][j][3] + bv.y);
            if (permute) {
                int h = col >> 6, dd = col & 63;
                *(float2*)(C + ((size_t)((rowA >> 10) * HH + h) * NQ + (rowA & 1023)) * 64 + dd) = vA;
                *(float2*)(C + ((size_t)((rowB >> 10) * HH + h) * NQ + (rowB & 1023)) * 64 + dd) = vB;
            } else {
                *(float2*)(C + (size_t)rowA * 512 + col) = vA;
                *(float2*)(C + (size_t)rowB * 512 + col) = vB;
            }
        }
    }
}

// =====================================================================
// bias_mma: D[k=128][bh=64] = R[q][k0+.][d] @ Qh[.][q][d]^T, 3-split.
// 8 warps (4m x 2n), warp tile 32x32. Transpose epilogue -> Sb fp32.
// Grid (8, 1024).
// =====================================================================
#define BZ_RH 0
#define BZ_RL 18432
#define BZ_QH 36864
#define BZ_QL 46080
#define BIAS_SMEM 55296

__global__ __launch_bounds__(256) void bias_mma(
    const float* __restrict__ Qh, const float* __restrict__ R,
    float* __restrict__ Sb)
{
    extern __shared__ __align__(128) char smem[];
    u32 sb = smem_u32(smem);
    int tid = threadIdx.x, wid = tid >> 5, lane = tid & 31;
    int wm = wid & 3, wn = wid >> 2;
    int q = blockIdx.y, k0 = blockIdx.x * 128;

#pragma unroll
    for (int r = 0; r < 8; r++) {
        int idx = tid + r * 256;
        int row = idx >> 4, col = (idx & 15) << 2;
        float4 v = *(const float4*)(R + ((size_t)q * NKV + k0 + row) * DHD + col);
        ull h8, l8; split4(v, h8, l8);
        *(ull*)(smem + BZ_RH + (row * 72 + col) * 2) = h8;
        *(ull*)(smem + BZ_RL + (row * 72 + col) * 2) = l8;
    }
#pragma unroll
    for (int r = 0; r < 4; r++) {
        int idx = tid + r * 256;
        int row = idx >> 4, col = (idx & 15) << 2;
        float4 v = *(const float4*)(Qh + ((size_t)row * NQ + q) * DHD + col);
        ull h8, l8; split4(v, h8, l8);
        *(ull*)(smem + BZ_QH + (row * 72 + col) * 2) = h8;
        *(ull*)(smem + BZ_QL + (row * 72 + col) * 2) = l8;
    }
    __syncthreads();

    float acc[2][4][4];
#pragma unroll
    for (int m = 0; m < 2; m++)
#pragma unroll
        for (int j = 0; j < 4; j++)
#pragma unroll
            for (int t = 0; t < 4; t++) acc[m][j][t] = 0.f;

#pragma unroll
    for (int ks = 0; ks < 64; ks += 16) {
        u32 ah[2][4], al[2][4];
#pragma unroll
        for (int f = 0; f < 2; f++) {
            u32 ra = (u32)((wm * 32 + f * 16 + (lane & 15)) * 72 + ks + ((lane >> 4) << 3)) * 2;
            ldm_x4(ah[f], sb + BZ_RH + ra);
            ldm_x4(al[f], sb + BZ_RL + ra);
        }
#pragma unroll
        for (int g = 0; g < 2; g++) {
            u32 rb = (u32)((wn * 32 + g * 16 + (lane & 7) + ((lane >> 4) << 3)) * 72
                           + ks + (((lane >> 3) & 1) << 3)) * 2;
            u32 qh4[4], ql4[4];
            ldm_x4(qh4, sb + BZ_QH + rb);
            ldm_x4(ql4, sb + BZ_QL + rb);
#pragma unroll
            for (int m = 0; m < 2; m++) {
                mma_bf16(acc[m][g*2],   ah[m], qh4[0], qh4[1]);
                mma_bf16(acc[m][g*2],   ah[m], ql4[0], ql4[1]);
                mma_bf16(acc[m][g*2],   al[m], qh4[0], qh4[1]);
                mma_bf16(acc[m][g*2+1], ah[m], qh4[2], qh4[3]);
                mma_bf16(acc[m][g*2+1], ah[m], ql4[2], ql4[3]);
                mma_bf16(acc[m][g*2+1], al[m], qh4[2], qh4[3]);
            }
        }
    }
    __syncthreads();

    float* T = (float*)smem;   // [bh][k] stride 132
#pragma unroll
    for (int m = 0; m < 2; m++) {
        int krow = wm * 32 + m * 16 + (lane >> 2);
#pragma unroll
        for (int j = 0; j < 4; j++) {
            int bhc = wn * 32 + j * 8 + (lane & 3) * 2;
            T[bhc * 132 + krow]           = acc[m][j][0];
            T[(bhc + 1) * 132 + krow]     = acc[m][j][1];
            T[bhc * 132 + krow + 8]       = acc[m][j][2];
            T[(bhc + 1) * 132 + krow + 8] = acc[m][j][3];
        }
    }
    __syncthreads();

    int bh2 = tid >> 2, part = tid & 3;
    float* dst = Sb + ((size_t)q * BHN + bh2) * NKV + k0 + part * 32;
#pragma unroll
    for (int j = 0; j < 8; j++)
        *(float4*)(dst + j * 4) = *(float4*)&T[bh2 * 132 + part * 32 + j * 4];
}

// =====================================================================
// attn_kernel: UNCHANGED known-good f32x2 version.
// =====================================================================
#define SROW 1028
#define QS2_OFF (32*SROW)
#define KS_OFF  (QS2_OFF + 64*72)
#define MB_OFF  (KS_OFF + 64*260)
#define ATTN_SMEM ((MB_OFF + 1024)*4)

__global__ __launch_bounds__(256) void attn_kernel(
    const float* __restrict__ Qh, const float* __restrict__ Kh,
    const float* __restrict__ Vh, const float* __restrict__ Sb,
    const int* __restrict__ mask, float* __restrict__ attn,
    float* __restrict__ ctx)
{
    extern __shared__ float sm[];
    float* S   = sm;
    float* Qs2 = sm + QS2_OFF;
    float* Ks  = sm + KS_OFF;
    float* mb  = sm + MB_OFF;
    int tid = threadIdx.x;
    int bh  = blockIdx.x;
    int q0  = blockIdx.y * 32;
    int b = bh >> 3, h = bh & 7;

    for (int idx = tid; idx < 32*16; idx += 256) {
        int qq = idx >> 4, d0 = (idx & 15) << 2;
        float4 v = *(const float4*)&Qh[((size_t)bh*NQ + q0 + qq)*DHD + d0];
        Qs2[(d0+0)*72 + 2*qq] = v.x; Qs2[(d0+0)*72 + 2*qq+1] = v.x;
        Qs2[(d0+1)*72 + 2*qq] = v.y; Qs2[(d0+1)*72 + 2*qq+1] = v.y;
        Qs2[(d0+2)*72 + 2*qq] = v.z; Qs2[(d0+2)*72 + 2*qq+1] = v.z;
        Qs2[(d0+3)*72 + 2*qq] = v.w; Qs2[(d0+3)*72 + 2*qq+1] = v.w;
    }
    for (int k = tid; k < NKV; k += 256)
        mb[k] = mask[b*NKV + k] ? 0.f : -1e30f;

    const float scale = 0.125f;
    int kg = tid & 31, qg = tid >> 5;

    for (int c = 0; c < 4; c++) {
        __syncthreads();
        for (int idx = tid; idx < 256*16; idx += 256) {
            int kk = idx >> 4, d0 = (idx & 15) << 2;
            float4 v = *(const float4*)&Kh[((size_t)bh*NKV + c*256 + kk)*DHD + d0];
            Ks[(d0+0)*260 + kk] = v.x;
            Ks[(d0+1)*260 + kk] = v.y;
            Ks[(d0+2)*260 + kk] = v.z;
            Ks[(d0+3)*260 + kk] = v.w;
        }
        __syncthreads();

        ull acc[4][4];
#pragma unroll
        for (int i = 0; i < 4; i++)
#pragma unroll
            for (int j = 0; j < 4; j++) acc[i][j] = 0ULL;

#pragma unroll 4
        for (int d = 0; d < 64; d++) {
            ulonglong2 QA = *(const ulonglong2*)&Qs2[d*72 + qg*8];
            ulonglong2 QB = *(const ulonglong2*)&Qs2[d*72 + qg*8 + 4];
            ulonglong2 K0 = *(const ulonglong2*)&Ks[d*260 + kg*4];
            ulonglong2 K1 = *(const ulonglong2*)&Ks[d*260 + 128 + kg*4];
            ull av[4] = {QA.x, QA.y, QB.x, QB.y};
#pragma unroll
            for (int i = 0; i < 4; i++) {
                FMA2(acc[i][0], av[i], K0.x);
                FMA2(acc[i][1], av[i], K0.y);
                FMA2(acc[i][2], av[i], K1.x);
                FMA2(acc[i][3], av[i], K1.y);
            }
        }

        int cb = c*256;
#pragma unroll
        for (int i = 0; i < 4; i++) {
            int qq = qg*4 + i;
            const float* sbrow = Sb + ((size_t)(q0+qq)*BHN + bh)*NKV + cb;
            float4 b0 = *(const float4*)(sbrow + kg*4);
            float4 b1 = *(const float4*)(sbrow + 128 + kg*4);
            float4 m0 = *(const float4*)&mb[cb + kg*4];
            float4 m1 = *(const float4*)&mb[cb + 128 + kg*4];
            float2 p0 = unpk(acc[i][0]), p1 = unpk(acc[i][1]);
            float2 p2 = unpk(acc[i][2]), p3 = unpk(acc[i][3]);
            float4 r0, r1;
            r0.x = (p0.x + b0.x)*scale + m0.x;
            r0.y = (p0.y + b0.y)*scale + m0.y;
            r0.z = (p1.x + b0.z)*scale + m0.z;
            r0.w = (p1.y + b0.w)*scale + m0.w;
            r1.x = (p2.x + b1.x)*scale + m1.x;
            r1.y = (p2.y + b1.y)*scale + m1.y;
            r1.z = (p3.x + b1.z)*scale + m1.z;
            r1.w = (p3.y + b1.w)*scale + m1.w;
            *(float4*)&S[qq*SROW + cb + kg*4]       = r0;
            *(float4*)&S[qq*SROW + cb + 128 + kg*4] = r1;
        }
    }
    __syncthreads();

    int lane = tid & 31, wid = tid >> 5;
    for (int r = 0; r < 4; r++) {
        float* row = S + (wid*4 + r)*SROW;
        float m = -3.4e38f;
        for (int k = lane; k < NKV; k += 32) m = fmaxf(m, row[k]);
#pragma unroll
        for (int o = 16; o; o >>= 1) m = fmaxf(m, __shfl_xor_sync(0xffffffffu, m, o));
        float s = 0.f;
        for (int k = lane; k < NKV; k += 32) {
            float e = __expf(row[k] - m);
            row[k] = e; s += e;
        }
#pragma unroll
        for (int o = 16; o; o >>= 1) s += __shfl_xor_sync(0xffffffffu, s, o);
        float inv = 1.f / s;
        __syncwarp();
        float* arow = attn + ((size_t)bh*NQ + q0 + wid*4 + r)*NKV;
        for (int k = lane*4; k < NKV; k += 128) {
            float4 v = *(float4*)&row[k];
            v.x *= inv; v.y *= inv; v.z *= inv; v.w *= inv;
            *(float4*)&row[k] = v;
            *(float4*)&arow[k] = v;
        }
        __syncwarp();
    }
    __syncthreads();

    int half = tid >> 7;
    int t    = tid & 127;
    int qg2  = t >> 4;
    int dg   = t & 15;
    float* Vs = Ks + half * (64*68);

    ull acc[4][2];
#pragma unroll
    for (int i = 0; i < 4; i++) { acc[i][0] = 0ULL; acc[i][1] = 0ULL; }

    for (int kb = 0; kb < 8; kb++) {
        int koff = half*512 + kb*64;
        for (int r = 0; r < 8; r++) {
            int idx = t + r*128;
            int kk = idx >> 4, d0 = (idx & 15) << 2;
            *(float4*)&Vs[kk*68 + d0] =
                *(const float4*)&Vh[((size_t)bh*NKV + koff + kk)*DHD + d0];
        }
        __syncthreads();
#pragma unroll 2
        for (int kk4 = 0; kk4 < 16; kk4++) {
            float4 p[4];
#pragma unroll
            for (int i = 0; i < 4; i++)
                p[i] = *(float4*)&S[(qg2*4 + i)*SROW + koff + kk4*4];
#pragma unroll
            for (int tt = 0; tt < 4; tt++) {
                ulonglong2 v = *(const ulonglong2*)&Vs[(kk4*4 + tt)*68 + dg*4];
                float pv[4] = { tt==0?p[0].x: tt==1?p[0].y: tt==2?p[0].z:p[0].w,
                                tt==0?p[1].x: tt==1?p[1].y: tt==2?p[1].z:p[1].w,
                                tt==0?p[2].x: tt==1?p[2].y: tt==2?p[2].z:p[2].w,
                                tt==0?p[3].x: tt==1?p[3].y: tt==2?p[3].z:p[3].w };
#pragma unroll
                for (int i = 0; i < 4; i++) {
                    ull pd = dup2(pv[i]);
                    FMA2(acc[i][0], pd, v.x);
                    FMA2(acc[i][1], pd, v.y);
                }
            }
        }
        __syncthreads();
    }

    float* scr = Qs2;
    if (half == 1) {
#pragma unroll
        for (int i = 0; i < 4; i++) {
            float2 a = unpk(acc[i][0]), c2 = unpk(acc[i][1]);
            *(float4*)&scr[(qg2*4 + i)*64 + dg*4] = make_float4(a.x, a.y, c2.x, c2.y);
        }
    }
    __syncthreads();
    if (half == 0) {
#pragma unroll
        for (int i = 0; i < 4; i++) {
            int qq = qg2*4 + i;
            float4 o = *(float4*)&scr[qq*64 + dg*4];
            float2 a = unpk(acc[i][0]), c2 = unpk(acc[i][1]);
            o.x += a.x; o.y += a.y; o.z += c2.x; o.w += c2.y;
            *(float4*)(ctx + ((size_t)b*NQ + q0 + qq)*DM + h*DHD + dg*4) = o;
        }
    }
}

// =====================================================================
// launcher
// =====================================================================
extern "C" void kernel_launch(void* const* d_in, const int* in_sizes, int n_in,
                              void* d_out, int out_size)
{
    const float* q    = (const float*)d_in[0];
    const float* kv   = (const float*)d_in[1];
    const int*   mask = (const int*)  d_in[2];
    const float* Wq   = (const float*)d_in[3];
    const float* bq   = (const float*)d_in[4];
    const float* Wk   = (const float*)d_in[5];
    const float* bk   = (const float*)d_in[6];
    const float* Wv   = (const float*)d_in[7];
    const float* bv   = (const float*)d_in[8];
    const float* Wo   = (const float*)d_in[9];
    const float* bo   = (const float*)d_in[10];
    const float* R    = (const float*)d_in[11];

    float* out = (float*)d_out;
    const size_t out_elems  = (size_t)BB*NQ*DM;
    const size_t attn_elems = (size_t)BHN*NQ*NKV;

    float *Qh, *Kh, *Vh, *Sb, *ctx, *attn_fb;
    cudaGetSymbolAddress((void**)&Qh,  g_Qh);
    cudaGetSymbolAddress((void**)&Kh,  g_Kh);
    cudaGetSymbolAddress((void**)&Vh,  g_Vh);
    cudaGetSymbolAddress((void**)&Sb,  g_Sb);
    cudaGetSymbolAddress((void**)&ctx, g_ctx);
    cudaGetSymbolAddress((void**)&attn_fb, g_attn_fallback);

    float* attn = ((size_t)out_size >= out_elems + attn_elems)
                ? (out + out_elems) : attn_fb;

    cudaFuncSetAttribute(proj_mma, cudaFuncAttributeMaxDynamicSharedMemorySize, PROJ_SMEM);
    cudaFuncSetAttribute(bias_mma, cudaFuncAttributeMaxDynamicSharedMemorySize, BIAS_SMEM);
    cudaFuncSetAttribute(attn_kernel, cudaFuncAttributeMaxDynamicSharedMemorySize, ATTN_SMEM);

    dim3 gProj(4, 64);
    proj_mma<<<gProj, 256, PROJ_SMEM>>>(q,  Wq, bq, Qh, 1);
    proj_mma<<<gProj, 256, PROJ_SMEM>>>(kv, Wk, bk, Kh, 1);
    proj_mma<<<gProj, 256, PROJ_SMEM>>>(kv, Wv, bv, Vh, 1);

    bias_mma<<<dim3(8, 1024), 256, BIAS_SMEM>>>(Qh, R, Sb);

    attn_kernel<<<dim3(64, 32), 256, ATTN_SMEM>>>(Qh, Kh, Vh, Sb, mask, attn, ctx);

    proj_mma<<<gProj, 256, PROJ_SMEM>>>(ctx, Wo, bo, out, 0);
}

// round 8
// speedup vs baseline: 1.8386x; 1.4368x over previous
#include <cuda_runtime.h>
#include <cuda_bf16.h>
#include <cstdint>
#include <cstddef>

#define BB    8
#define HH    8
#define NQ    1024
#define NKV   1024
#define DHD   64
#define DM    512
#define BHN   (BB*HH)

typedef unsigned long long ull;
typedef uint32_t u32;

__device__ __forceinline__ u32 smem_u32(const void* p) {
    u32 a;
    asm("{ .reg .u64 t; cvta.to.shared.u64 t, %1; cvt.u32.u64 %0, t; }" : "=r"(a) : "l"(p));
    return a;
}
__device__ __forceinline__ void ldm_x4(u32* r, u32 a) {
    asm volatile("ldmatrix.sync.aligned.m8n8.x4.shared.b16 {%0,%1,%2,%3}, [%4];"
        : "=r"(r[0]),"=r"(r[1]),"=r"(r[2]),"=r"(r[3]) : "r"(a));
}
__device__ __forceinline__ void ldm_x4t(u32* r, u32 a) {
    asm volatile("ldmatrix.sync.aligned.m8n8.x4.trans.shared.b16 {%0,%1,%2,%3}, [%4];"
        : "=r"(r[0]),"=r"(r[1]),"=r"(r[2]),"=r"(r[3]) : "r"(a));
}
__device__ __forceinline__ void mma_bf16(float* c, const u32* a, u32 b0, u32 b1) {
    asm volatile("mma.sync.aligned.m16n8k16.row.col.f32.bf16.bf16.f32 "
        "{%0,%1,%2,%3}, {%4,%5,%6,%7}, {%8,%9}, {%0,%1,%2,%3};"
        : "+f"(c[0]),"+f"(c[1]),"+f"(c[2]),"+f"(c[3])
        : "r"(a[0]),"r"(a[1]),"r"(a[2]),"r"(a[3]), "r"(b0),"r"(b1));
}
__device__ __forceinline__ void split4(float4 v, ull& hi8, ull& lo8) {
    __nv_bfloat162 h01 = __floats2bfloat162_rn(v.x, v.y);
    __nv_bfloat162 h23 = __floats2bfloat162_rn(v.z, v.w);
    float2 f01 = __bfloat1622float2(h01);
    float2 f23 = __bfloat1622float2(h23);
    __nv_bfloat162 l01 = __floats2bfloat162_rn(v.x - f01.x, v.y - f01.y);
    __nv_bfloat162 l23 = __floats2bfloat162_rn(v.z - f23.x, v.w - f23.y);
    u32 uh0 = *(u32*)&h01, uh1 = *(u32*)&h23;
    u32 ul0 = *(u32*)&l01, ul1 = *(u32*)&l23;
    hi8 = (ull)uh0 | ((ull)uh1 << 32);
    lo8 = (ull)ul0 | ((ull)ul1 << 32);
}
__device__ __forceinline__ void split2(float2 v, u32& h, u32& l) {
    __nv_bfloat162 hb = __floats2bfloat162_rn(v.x, v.y);
    float2 hf = __bfloat1622float2(hb);
    __nv_bfloat162 lb = __floats2bfloat162_rn(v.x - hf.x, v.y - hf.y);
    h = *(u32*)&hb; l = *(u32*)&lb;
}

// ---------------- device scratch ----------------
__device__ float g_Qh[(size_t)BHN*NQ*DHD];
__device__ float g_Kh[(size_t)BHN*NKV*DHD];
__device__ float g_Vh[(size_t)BHN*NKV*DHD];
__device__ float g_Sb[(size_t)NQ*BHN*NKV];
__device__ float g_ctx[(size_t)BB*NQ*DM];
__device__ float g_attn_fallback[(size_t)BHN*NQ*NKV];

// =====================================================================
// proj_mma: unchanged (round-6, passing).
// =====================================================================
#define PJ_AH 0
#define PJ_AL 10240
#define PJ_WH 20480
#define PJ_WL 29184
#define PROJ_SMEM 37888

__global__ __launch_bounds__(256) void proj_mma(
    const float* __restrict__ A, const float* __restrict__ W,
    const float* __restrict__ bias, float* __restrict__ C, int permute)
{
    extern __shared__ __align__(128) char smem[];
    u32 sb = smem_u32(smem);
    int tid = threadIdx.x, wid = tid >> 5, lane = tid & 31;
    int m0 = blockIdx.y * 128, n0 = blockIdx.x * 128;
    int wm = wid & 3, wn = wid >> 2;

    float acc[2][8][4];
#pragma unroll
    for (int m = 0; m < 2; m++)
#pragma unroll
        for (int j = 0; j < 8; j++)
#pragma unroll
            for (int t = 0; t < 4; t++) acc[m][j][t] = 0.f;

    float4 pa[4], pw[4];
#pragma unroll
    for (int r = 0; r < 4; r++) {
        int idx = tid + r * 256;
        pa[r] = *(const float4*)(A + (size_t)(m0 + (idx >> 3)) * 512 + ((idx & 7) << 2));
        pw[r] = *(const float4*)(W + (size_t)(idx >> 5) * 512 + n0 + ((idx & 31) << 2));
    }

    for (int kb = 0; kb < 16; kb++) {
        if (kb) __syncthreads();
#pragma unroll
        for (int r = 0; r < 4; r++) {
            int idx = tid + r * 256;
            {
                int row = idx >> 3, col = (idx & 7) << 2;
                ull h8, l8; split4(pa[r], h8, l8);
                *(ull*)(smem + PJ_AH + (row * 40 + col) * 2) = h8;
                *(ull*)(smem + PJ_AL + (row * 40 + col) * 2) = l8;
            }
            {
                int row = idx >> 5, col = (idx & 31) << 2;
                ull h8, l8; split4(pw[r], h8, l8);
                *(ull*)(smem + PJ_WH + (row * 136 + col) * 2) = h8;
                *(ull*)(smem + PJ_WL + (row * 136 + col) * 2) = l8;
            }
        }
        __syncthreads();
        if (kb < 15) {
            int k0 = (kb + 1) * 32;
#pragma unroll
            for (int r = 0; r < 4; r++) {
                int idx = tid + r * 256;
                pa[r] = *(const float4*)(A + (size_t)(m0 + (idx >> 3)) * 512 + k0 + ((idx & 7) << 2));
                pw[r] = *(const float4*)(W + (size_t)(k0 + (idx >> 5)) * 512 + n0 + ((idx & 31) << 2));
            }
        }
#pragma unroll
        for (int ks = 0; ks < 32; ks += 16) {
            u32 ah[2][4], al[2][4];
#pragma unroll
            for (int f = 0; f < 2; f++) {
                u32 ra = (u32)((wm * 32 + f * 16 + (lane & 15)) * 40 + ks + ((lane >> 4) << 3)) * 2;
                ldm_x4(ah[f], sb + PJ_AH + ra);
                ldm_x4(al[f], sb + PJ_AL + ra);
            }
#pragma unroll
            for (int nf = 0; nf < 4; nf++) {
                u32 rb = (u32)((ks + (lane & 15)) * 136 + wn * 64 + nf * 16 + ((lane >> 4) << 3)) * 2;
                u32 bh4[4], bl4[4];
                ldm_x4t(bh4, sb + PJ_WH + rb);
                ldm_x4t(bl4, sb + PJ_WL + rb);
#pragma unroll
                for (int m = 0; m < 2; m++) {
                    mma_bf16(acc[m][nf*2],   ah[m], bh4[0], bh4[1]);
                    mma_bf16(acc[m][nf*2],   ah[m], bl4[0], bl4[1]);
                    mma_bf16(acc[m][nf*2],   al[m], bh4[0], bh4[1]);
                    mma_bf16(acc[m][nf*2+1], ah[m], bh4[2], bh4[3]);
                    mma_bf16(acc[m][nf*2+1], ah[m], bl4[2], bl4[3]);
                    mma_bf16(acc[m][nf*2+1], al[m], bh4[2], bh4[3]);
                }
            }
        }
    }

    int r0 = m0 + wm * 32 + (lane >> 2);
    int cb = n0 + wn * 64 + (lane & 3) * 2;
#pragma unroll
    for (int m = 0; m < 2; m++) {
#pragma unroll
        for (int j = 0; j < 8; j++) {
            int col = cb + j * 8;
            float2 bv = *(const float2*)&bias[col];
            int rowA = r0 + m * 16, rowB = rowA + 8;
            float2 vA = make_float2(acc[m][j][0] + bv.x, acc[m][j][1] + bv.y);
            float2 vB = make_float2(acc[m][j][2] + bv.x, acc[m][j][3] + bv.y);
            if (permute) {
                int h = col >> 6, dd = col & 63;
                *(float2*)(C + ((size_t)((rowA >> 10) * HH + h) * NQ + (rowA & 1023)) * 64 + dd) = vA;
                *(float2*)(C + ((size_t)((rowB >> 10) * HH + h) * NQ + (rowB & 1023)) * 64 + dd) = vB;
            } else {
                *(float2*)(C + (size_t)rowA * 512 + col) = vA;
                *(float2*)(C + (size_t)rowB * 512 + col) = vB;
            }
        }
    }
}

// =====================================================================
// bias_mma: unchanged (round-6, passing).
// =====================================================================
#define BZ_RH 0
#define BZ_RL 18432
#define BZ_QH 36864
#define BZ_QL 46080
#define BIAS_SMEM 55296

__global__ __launch_bounds__(256) void bias_mma(
    const float* __restrict__ Qh, const float* __restrict__ R,
    float* __restrict__ Sb)
{
    extern __shared__ __align__(128) char smem[];
    u32 sb = smem_u32(smem);
    int tid = threadIdx.x, wid = tid >> 5, lane = tid & 31;
    int wm = wid & 3, wn = wid >> 2;
    int q = blockIdx.y, k0 = blockIdx.x * 128;

#pragma unroll
    for (int r = 0; r < 8; r++) {
        int idx = tid + r * 256;
        int row = idx >> 4, col = (idx & 15) << 2;
        float4 v = *(const float4*)(R + ((size_t)q * NKV + k0 + row) * DHD + col);
        ull h8, l8; split4(v, h8, l8);
        *(ull*)(smem + BZ_RH + (row * 72 + col) * 2) = h8;
        *(ull*)(smem + BZ_RL + (row * 72 + col) * 2) = l8;
    }
#pragma unroll
    for (int r = 0; r < 4; r++) {
        int idx = tid + r * 256;
        int row = idx >> 4, col = (idx & 15) << 2;
        float4 v = *(const float4*)(Qh + ((size_t)row * NQ + q) * DHD + col);
        ull h8, l8; split4(v, h8, l8);
        *(ull*)(smem + BZ_QH + (row * 72 + col) * 2) = h8;
        *(ull*)(smem + BZ_QL + (row * 72 + col) * 2) = l8;
    }
    __syncthreads();

    float acc[2][4][4];
#pragma unroll
    for (int m = 0; m < 2; m++)
#pragma unroll
        for (int j = 0; j < 4; j++)
#pragma unroll
            for (int t = 0; t < 4; t++) acc[m][j][t] = 0.f;

#pragma unroll
    for (int ks = 0; ks < 64; ks += 16) {
        u32 ah[2][4], al[2][4];
#pragma unroll
        for (int f = 0; f < 2; f++) {
            u32 ra = (u32)((wm * 32 + f * 16 + (lane & 15)) * 72 + ks + ((lane >> 4) << 3)) * 2;
            ldm_x4(ah[f], sb + BZ_RH + ra);
            ldm_x4(al[f], sb + BZ_RL + ra);
        }
#pragma unroll
        for (int g = 0; g < 2; g++) {
            u32 rb = (u32)((wn * 32 + g * 16 + (lane & 7) + ((lane >> 4) << 3)) * 72
                           + ks + (((lane >> 3) & 1) << 3)) * 2;
            u32 qh4[4], ql4[4];
            ldm_x4(qh4, sb + BZ_QH + rb);
            ldm_x4(ql4, sb + BZ_QL + rb);
#pragma unroll
            for (int m = 0; m < 2; m++) {
                mma_bf16(acc[m][g*2],   ah[m], qh4[0], qh4[1]);
                mma_bf16(acc[m][g*2],   ah[m], ql4[0], ql4[1]);
                mma_bf16(acc[m][g*2],   al[m], qh4[0], qh4[1]);
                mma_bf16(acc[m][g*2+1], ah[m], qh4[2], qh4[3]);
                mma_bf16(acc[m][g*2+1], ah[m], ql4[2], ql4[3]);
                mma_bf16(acc[m][g*2+1], al[m], qh4[2], qh4[3]);
            }
        }
    }
    __syncthreads();

    float* T = (float*)smem;   // [bh][k] stride 132
#pragma unroll
    for (int m = 0; m < 2; m++) {
        int krow = wm * 32 + m * 16 + (lane >> 2);
#pragma unroll
        for (int j = 0; j < 4; j++) {
            int bhc = wn * 32 + j * 8 + (lane & 3) * 2;
            T[bhc * 132 + krow]           = acc[m][j][0];
            T[(bhc + 1) * 132 + krow]     = acc[m][j][1];
            T[bhc * 132 + krow + 8]       = acc[m][j][2];
            T[(bhc + 1) * 132 + krow + 8] = acc[m][j][3];
        }
    }
    __syncthreads();

    int bh2 = tid >> 2, part = tid & 3;
    float* dst = Sb + ((size_t)q * BHN + bh2) * NKV + k0 + part * 32;
#pragma unroll
    for (int j = 0; j < 8; j++)
        *(float4*)(dst + j * 4) = *(float4*)&T[bh2 * 132 + part * 32 + j * 4];
}

// =====================================================================
// attn_mma: CTA per (bh, 32-q tile), 256 thr, tensor-core QK^T and P@V.
// =====================================================================
#define SROW  1028
#define AS_MB 131584
#define AS_QH 135680
#define AS_QL 140288
#define AS_KH 144896
#define AS_KL 181760
#define ATTN_SMEM 218624

__global__ __launch_bounds__(256) void attn_mma(
    const float* __restrict__ Qh, const float* __restrict__ Kh,
    const float* __restrict__ Vh, const float* __restrict__ Sb,
    const int* __restrict__ mask, float* __restrict__ attn,
    float* __restrict__ ctx)
{
    extern __shared__ __align__(128) char smem[];
    u32 sbp = smem_u32(smem);
    float* S  = (float*)smem;
    float* mb = (float*)(smem + AS_MB);
    int tid = threadIdx.x, wid = tid >> 5, lane = tid & 31;
    int bh  = blockIdx.x;
    int q0  = blockIdx.y * 32;
    int b = bh >> 3, h = bh & 7;
    const float scale = 0.125f;

    // Q tile -> bf16 hi/lo smem
#pragma unroll
    for (int r = 0; r < 2; r++) {
        int idx = tid + r * 256;
        int row = idx >> 4, col = (idx & 15) << 2;
        float4 v = *(const float4*)(Qh + ((size_t)bh * NQ + q0 + row) * DHD + col);
        ull h8, l8; split4(v, h8, l8);
        *(ull*)(smem + AS_QH + (row * 72 + col) * 2) = h8;
        *(ull*)(smem + AS_QL + (row * 72 + col) * 2) = l8;
    }
    for (int k = tid; k < NKV; k += 256)
        mb[k] = mask[b * NKV + k] ? 0.f : -1e30f;
    __syncthreads();

    // hoist Q fragments: 4 d-steps x 2 m
    u32 qh[4][2][4], ql[4][2][4];
#pragma unroll
    for (int ds = 0; ds < 4; ds++)
#pragma unroll
        for (int m = 0; m < 2; m++) {
            u32 ra = (u32)((m * 16 + (lane & 15)) * 72 + ds * 16 + ((lane >> 4) << 3)) * 2;
            ldm_x4(qh[ds][m], sbp + AS_QH + ra);
            ldm_x4(ql[ds][m], sbp + AS_QL + ra);
        }

    // ---- Phase 1: QK^T + Sb + mask, chunks of 256 k ----
    for (int c = 0; c < 4; c++) {
        __syncthreads();
#pragma unroll
        for (int r = 0; r < 16; r++) {
            int idx = tid + r * 256;
            int row = idx >> 4, col = (idx & 15) << 2;
            float4 v = *(const float4*)(Kh + ((size_t)bh * NKV + c * 256 + row) * DHD + col);
            ull h8, l8; split4(v, h8, l8);
            *(ull*)(smem + AS_KH + (row * 72 + col) * 2) = h8;
            *(ull*)(smem + AS_KL + (row * 72 + col) * 2) = l8;
        }
        __syncthreads();

        float acc[2][4][4];
#pragma unroll
        for (int m = 0; m < 2; m++)
#pragma unroll
            for (int j = 0; j < 4; j++)
#pragma unroll
                for (int t = 0; t < 4; t++) acc[m][j][t] = 0.f;

#pragma unroll
        for (int ds = 0; ds < 4; ds++) {
#pragma unroll
            for (int g = 0; g < 2; g++) {
                // A-style addressing: mat order = [n0-7][k0-7],[n8-15][k0-7],
                // [n0-7][k8-15],[n8-15][k8-15] -> B pairs are (0,2) and (1,3).
                u32 rb = (u32)((wid * 32 + g * 16 + (lane & 15)) * 72 + ds * 16 + ((lane >> 4) << 3)) * 2;
                u32 kh4[4], kl4[4];
                ldm_x4(kh4, sbp + AS_KH + rb);
                ldm_x4(kl4, sbp + AS_KL + rb);
#pragma unroll
                for (int m = 0; m < 2; m++) {
                    mma_bf16(acc[m][g*2],   qh[ds][m], kh4[0], kh4[2]);
                    mma_bf16(acc[m][g*2],   qh[ds][m], kl4[0], kl4[2]);
                    mma_bf16(acc[m][g*2],   ql[ds][m], kh4[0], kh4[2]);
                    mma_bf16(acc[m][g*2+1], qh[ds][m], kh4[1], kh4[3]);
                    mma_bf16(acc[m][g*2+1], qh[ds][m], kl4[1], kl4[3]);
                    mma_bf16(acc[m][g*2+1], ql[ds][m], kh4[1], kh4[3]);
                }
            }
        }
        // epilogue: S = (acc + Sb)*scale + mask
#pragma unroll
        for (int m = 0; m < 2; m++) {
            int qq = m * 16 + (lane >> 2);
#pragma unroll
            for (int j = 0; j < 4; j++) {
                int k = c * 256 + wid * 32 + j * 8 + (lane & 3) * 2;
                const float* s0 = Sb + ((size_t)(q0 + qq) * BHN + bh) * NKV + k;
                const float* s1 = Sb + ((size_t)(q0 + qq + 8) * BHN + bh) * NKV + k;
                float2 b0 = *(const float2*)s0;
                float2 b1 = *(const float2*)s1;
                float2 mm = *(const float2*)&mb[k];
                float2 v0 = make_float2((acc[m][j][0] + b0.x) * scale + mm.x,
                                        (acc[m][j][1] + b0.y) * scale + mm.y);
                float2 v1 = make_float2((acc[m][j][2] + b1.x) * scale + mm.x,
                                        (acc[m][j][3] + b1.y) * scale + mm.y);
                *(float2*)&S[qq * SROW + k]       = v0;
                *(float2*)&S[(qq + 8) * SROW + k] = v1;
            }
        }
    }
    __syncthreads();

    // ---- Phase 2: softmax + attn store ----
    for (int r = 0; r < 4; r++) {
        float* row = S + (wid * 4 + r) * SROW;
        float m = -3.4e38f;
        for (int k = lane; k < NKV; k += 32) m = fmaxf(m, row[k]);
#pragma unroll
        for (int o = 16; o; o >>= 1) m = fmaxf(m, __shfl_xor_sync(0xffffffffu, m, o));
        float s = 0.f;
        for (int k = lane; k < NKV; k += 32) {
            float e = __expf(row[k] - m);
            row[k] = e; s += e;
        }
#pragma unroll
        for (int o = 16; o; o >>= 1) s += __shfl_xor_sync(0xffffffffu, s, o);
        float inv = 1.f / s;
        __syncwarp();
        float* arow = attn + ((size_t)bh * NQ + q0 + wid * 4 + r) * NKV;
        for (int k = lane * 4; k < NKV; k += 128) {
            float4 v = *(float4*)&row[k];
            v.x *= inv; v.y *= inv; v.z *= inv; v.w *= inv;
            *(float4*)&row[k] = v;
            *(float4*)&arow[k] = v;
        }
        __syncwarp();
    }

    // ---- Phase 3: ctx = P @ V (tensor core, warp k-split + slab reduce) ----
    float acc[2][8][4];
#pragma unroll
    for (int m = 0; m < 2; m++)
#pragma unroll
        for (int j = 0; j < 8; j++)
#pragma unroll
            for (int t = 0; t < 4; t++) acc[m][j][t] = 0.f;

    for (int c = 0; c < 4; c++) {
        __syncthreads();
#pragma unroll
        for (int r = 0; r < 16; r++) {
            int idx = tid + r * 256;
            int row = idx >> 4, col = (idx & 15) << 2;
            float4 v = *(const float4*)(Vh + ((size_t)bh * NKV + c * 256 + row) * DHD + col);
            ull h8, l8; split4(v, h8, l8);
            *(ull*)(smem + AS_KH + (row * 72 + col) * 2) = h8;
            *(ull*)(smem + AS_KL + (row * 72 + col) * 2) = l8;
        }
        __syncthreads();

#pragma unroll
        for (int ks = 0; ks < 2; ks++) {
            int kbase = c * 256 + wid * 32 + ks * 16;
            u32 ph[2][4], pl[2][4];
#pragma unroll
            for (int m = 0; m < 2; m++) {
                int r0 = m * 16 + (lane >> 2);
                const float* Sr0 = S + r0 * SROW;
                const float* Sr1 = S + (r0 + 8) * SROW;
                int cc = kbase + (lane & 3) * 2;
                split2(*(const float2*)(Sr0 + cc),     ph[m][0], pl[m][0]);
                split2(*(const float2*)(Sr1 + cc),     ph[m][1], pl[m][1]);
                split2(*(const float2*)(Sr0 + cc + 8), ph[m][2], pl[m][2]);
                split2(*(const float2*)(Sr1 + cc + 8), ph[m][3], pl[m][3]);
            }
#pragma unroll
            for (int dn = 0; dn < 4; dn++) {
                u32 rv = (u32)((wid * 32 + ks * 16 + (lane & 15)) * 72 + dn * 16 + ((lane >> 4) << 3)) * 2;
                u32 vh4[4], vl4[4];
                ldm_x4t(vh4, sbp + AS_KH + rv);
                ldm_x4t(vl4, sbp + AS_KL + rv);
#pragma unroll
                for (int m = 0; m < 2; m++) {
                    mma_bf16(acc[m][dn*2],   ph[m], vh4[0], vh4[1]);
                    mma_bf16(acc[m][dn*2],   ph[m], vl4[0], vl4[1]);
                    mma_bf16(acc[m][dn*2],   pl[m], vh4[0], vh4[1]);
                    mma_bf16(acc[m][dn*2+1], ph[m], vh4[2], vh4[3]);
                    mma_bf16(acc[m][dn*2+1], ph[m], vl4[2], vl4[3]);
                    mma_bf16(acc[m][dn*2+1], pl[m], vh4[2], vh4[3]);
                }
            }
        }
    }
    __syncthreads();

    // slab reduce over 8 warps: slab[w][q][d], stride 68
    float* slab = (float*)(smem + AS_KH);
#pragma unroll
    for (int m = 0; m < 2; m++) {
        int qq = m * 16 + (lane >> 2);
#pragma unroll
        for (int j = 0; j < 8; j++) {
            int d = j * 8 + (lane & 3) * 2;
            *(float2*)&slab[(wid * 32 + qq) * 68 + d]     = make_float2(acc[m][j][0], acc[m][j][1]);
            *(float2*)&slab[(wid * 32 + qq + 8) * 68 + d] = make_float2(acc[m][j][2], acc[m][j][3]);
        }
    }
    __syncthreads();

    {
        int qq = tid >> 3, db = (tid & 7) * 8;
        float s[8];
#pragma unroll
        for (int t = 0; t < 8; t++) s[t] = 0.f;
#pragma unroll
        for (int w = 0; w < 8; w++) {
            const float* p = &slab[(w * 32 + qq) * 68 + db];
#pragma unroll
            for (int t = 0; t < 8; t++) s[t] += p[t];
        }
        float* dst = ctx + ((size_t)b * NQ + q0 + qq) * DM + h * DHD + db;
#pragma unroll
        for (int t = 0; t < 8; t += 4)
            *(float4*)(dst + t) = make_float4(s[t], s[t+1], s[t+2], s[t+3]);
    }
}

// =====================================================================
// launcher
// =====================================================================
extern "C" void kernel_launch(void* const* d_in, const int* in_sizes, int n_in,
                              void* d_out, int out_size)
{
    const float* q    = (const float*)d_in[0];
    const float* kv   = (const float*)d_in[1];
    const int*   mask = (const int*)  d_in[2];
    const float* Wq   = (const float*)d_in[3];
    const float* bq   = (const float*)d_in[4];
    const float* Wk   = (const float*)d_in[5];
    const float* bk   = (const float*)d_in[6];
    const float* Wv   = (const float*)d_in[7];
    const float* bv   = (const float*)d_in[8];
    const float* Wo   = (const float*)d_in[9];
    const float* bo   = (const float*)d_in[10];
    const float* R    = (const float*)d_in[11];

    float* out = (float*)d_out;
    const size_t out_elems  = (size_t)BB*NQ*DM;
    const size_t attn_elems = (size_t)BHN*NQ*NKV;

    float *Qh, *Kh, *Vh, *Sb, *ctx, *attn_fb;
    cudaGetSymbolAddress((void**)&Qh,  g_Qh);
    cudaGetSymbolAddress((void**)&Kh,  g_Kh);
    cudaGetSymbolAddress((void**)&Vh,  g_Vh);
    cudaGetSymbolAddress((void**)&Sb,  g_Sb);
    cudaGetSymbolAddress((void**)&ctx, g_ctx);
    cudaGetSymbolAddress((void**)&attn_fb, g_attn_fallback);

    float* attn = ((size_t)out_size >= out_elems + attn_elems)
                ? (out + out_elems) : attn_fb;

    cudaFuncSetAttribute(proj_mma, cudaFuncAttributeMaxDynamicSharedMemorySize, PROJ_SMEM);
    cudaFuncSetAttribute(bias_mma, cudaFuncAttributeMaxDynamicSharedMemorySize, BIAS_SMEM);
    cudaFuncSetAttribute(attn_mma, cudaFuncAttributeMaxDynamicSharedMemorySize, ATTN_SMEM);

    dim3 gProj(4, 64);
    proj_mma<<<gProj, 256, PROJ_SMEM>>>(q,  Wq, bq, Qh, 1);
    proj_mma<<<gProj, 256, PROJ_SMEM>>>(kv, Wk, bk, Kh, 1);
    proj_mma<<<gProj, 256, PROJ_SMEM>>>(kv, Wv, bv, Vh, 1);

    bias_mma<<<dim3(8, 1024), 256, BIAS_SMEM>>>(Qh, R, Sb);

    attn_mma<<<dim3(64, 32), 256, ATTN_SMEM>>>(Qh, Kh, Vh, Sb, mask, attn, ctx);

    proj_mma<<<gProj, 256, PROJ_SMEM>>>(ctx, Wo, bo, out, 0);
}

// round 9
// speedup vs baseline: 2.1624x; 1.1761x over previous
#include <cuda_runtime.h>
#include <cuda_bf16.h>
#include <cstdint>
#include <cstddef>

#define BB    8
#define HH    8
#define NQ    1024
#define NKV   1024
#define DHD   64
#define DM    512
#define BHN   (BB*HH)

typedef unsigned long long ull;
typedef uint32_t u32;

__device__ __forceinline__ u32 smem_u32(const void* p) {
    u32 a;
    asm("{ .reg .u64 t; cvta.to.shared.u64 t, %1; cvt.u32.u64 %0, t; }" : "=r"(a) : "l"(p));
    return a;
}
__device__ __forceinline__ void ldm_x4(u32* r, u32 a) {
    asm volatile("ldmatrix.sync.aligned.m8n8.x4.shared.b16 {%0,%1,%2,%3}, [%4];"
        : "=r"(r[0]),"=r"(r[1]),"=r"(r[2]),"=r"(r[3]) : "r"(a));
}
__device__ __forceinline__ void ldm_x4t(u32* r, u32 a) {
    asm volatile("ldmatrix.sync.aligned.m8n8.x4.trans.shared.b16 {%0,%1,%2,%3}, [%4];"
        : "=r"(r[0]),"=r"(r[1]),"=r"(r[2]),"=r"(r[3]) : "r"(a));
}
__device__ __forceinline__ void mma_bf16(float* c, const u32* a, u32 b0, u32 b1) {
    asm volatile("mma.sync.aligned.m16n8k16.row.col.f32.bf16.bf16.f32 "
        "{%0,%1,%2,%3}, {%4,%5,%6,%7}, {%8,%9}, {%0,%1,%2,%3};"
        : "+f"(c[0]),"+f"(c[1]),"+f"(c[2]),"+f"(c[3])
        : "r"(a[0]),"r"(a[1]),"r"(a[2]),"r"(a[3]), "r"(b0),"r"(b1));
}
__device__ __forceinline__ void split4(float4 v, ull& hi8, ull& lo8) {
    __nv_bfloat162 h01 = __floats2bfloat162_rn(v.x, v.y);
    __nv_bfloat162 h23 = __floats2bfloat162_rn(v.z, v.w);
    float2 f01 = __bfloat1622float2(h01);
    float2 f23 = __bfloat1622float2(h23);
    __nv_bfloat162 l01 = __floats2bfloat162_rn(v.x - f01.x, v.y - f01.y);
    __nv_bfloat162 l23 = __floats2bfloat162_rn(v.z - f23.x, v.w - f23.y);
    u32 uh0 = *(u32*)&h01, uh1 = *(u32*)&h23;
    u32 ul0 = *(u32*)&l01, ul1 = *(u32*)&l23;
    hi8 = (ull)uh0 | ((ull)uh1 << 32);
    lo8 = (ull)ul0 | ((ull)ul1 << 32);
}
__device__ __forceinline__ void split2(float2 v, u32& h, u32& l) {
    __nv_bfloat162 hb = __floats2bfloat162_rn(v.x, v.y);
    float2 hf = __bfloat1622float2(hb);
    __nv_bfloat162 lb = __floats2bfloat162_rn(v.x - hf.x, v.y - hf.y);
    h = *(u32*)&hb; l = *(u32*)&lb;
}
__device__ __forceinline__ u32 pkbf(float x, float y) {
    __nv_bfloat162 t = __floats2bfloat162_rn(x, y);
    return *(u32*)&t;
}

#define CP_ASYNC16(dst, src) \
    asm volatile("cp.async.ca.shared.global [%0], [%1], 16;" :: "r"(dst), "l"(src) : "memory")
#define CP_COMMIT() asm volatile("cp.async.commit_group;" ::: "memory")
#define CP_WAIT0()  asm volatile("cp.async.wait_group 0;" ::: "memory")
#define CP_WAIT1()  asm volatile("cp.async.wait_group 1;" ::: "memory")

// ---------------- device scratch ----------------
__device__ __nv_bfloat16 g_Qhh[(size_t)BHN*NQ*DHD];
__device__ __nv_bfloat16 g_Qhl[(size_t)BHN*NQ*DHD];
__device__ __nv_bfloat16 g_Khh[(size_t)BHN*NKV*DHD];
__device__ __nv_bfloat16 g_Khl[(size_t)BHN*NKV*DHD];
__device__ __nv_bfloat16 g_Vhh[(size_t)BHN*NKV*DHD];
__device__ __nv_bfloat16 g_Vhl[(size_t)BHN*NKV*DHD];
__device__ __nv_bfloat16 g_Sb[(size_t)NQ*BHN*NKV];
__device__ float g_ctx[(size_t)BB*NQ*DM];
__device__ float g_attn_fallback[(size_t)BHN*NQ*NKV];

// =====================================================================
// proj_mma: C = A @ W + bias. permute=1 -> write bf16 hi/lo head arrays,
// permute=0 -> fp32 C.
// =====================================================================
#define PJ_AH 0
#define PJ_AL 10240
#define PJ_WH 20480
#define PJ_WL 29184
#define PROJ_SMEM 37888

__global__ __launch_bounds__(256) void proj_mma(
    const float* __restrict__ A, const float* __restrict__ W,
    const float* __restrict__ bias, float* __restrict__ C,
    __nv_bfloat16* __restrict__ Ohi, __nv_bfloat16* __restrict__ Olo,
    int permute)
{
    extern __shared__ __align__(128) char smem[];
    u32 sb = smem_u32(smem);
    int tid = threadIdx.x, wid = tid >> 5, lane = tid & 31;
    int m0 = blockIdx.y * 128, n0 = blockIdx.x * 128;
    int wm = wid & 3, wn = wid >> 2;

    float acc[2][8][4];
#pragma unroll
    for (int m = 0; m < 2; m++)
#pragma unroll
        for (int j = 0; j < 8; j++)
#pragma unroll
            for (int t = 0; t < 4; t++) acc[m][j][t] = 0.f;

    float4 pa[4], pw[4];
#pragma unroll
    for (int r = 0; r < 4; r++) {
        int idx = tid + r * 256;
        pa[r] = *(const float4*)(A + (size_t)(m0 + (idx >> 3)) * 512 + ((idx & 7) << 2));
        pw[r] = *(const float4*)(W + (size_t)(idx >> 5) * 512 + n0 + ((idx & 31) << 2));
    }

    for (int kb = 0; kb < 16; kb++) {
        if (kb) __syncthreads();
#pragma unroll
        for (int r = 0; r < 4; r++) {
            int idx = tid + r * 256;
            {
                int row = idx >> 3, col = (idx & 7) << 2;
                ull h8, l8; split4(pa[r], h8, l8);
                *(ull*)(smem + PJ_AH + (row * 40 + col) * 2) = h8;
                *(ull*)(smem + PJ_AL + (row * 40 + col) * 2) = l8;
            }
            {
                int row = idx >> 5, col = (idx & 31) << 2;
                ull h8, l8; split4(pw[r], h8, l8);
                *(ull*)(smem + PJ_WH + (row * 136 + col) * 2) = h8;
                *(ull*)(smem + PJ_WL + (row * 136 + col) * 2) = l8;
            }
        }
        __syncthreads();
        if (kb < 15) {
            int k0 = (kb + 1) * 32;
#pragma unroll
            for (int r = 0; r < 4; r++) {
                int idx = tid + r * 256;
                pa[r] = *(const float4*)(A + (size_t)(m0 + (idx >> 3)) * 512 + k0 + ((idx & 7) << 2));
                pw[r] = *(const float4*)(W + (size_t)(k0 + (idx >> 5)) * 512 + n0 + ((idx & 31) << 2));
            }
        }
#pragma unroll
        for (int ks = 0; ks < 32; ks += 16) {
            u32 ah[2][4], al[2][4];
#pragma unroll
            for (int f = 0; f < 2; f++) {
                u32 ra = (u32)((wm * 32 + f * 16 + (lane & 15)) * 40 + ks + ((lane >> 4) << 3)) * 2;
                ldm_x4(ah[f], sb + PJ_AH + ra);
                ldm_x4(al[f], sb + PJ_AL + ra);
            }
#pragma unroll
            for (int nf = 0; nf < 4; nf++) {
                u32 rb = (u32)((ks + (lane & 15)) * 136 + wn * 64 + nf * 16 + ((lane >> 4) << 3)) * 2;
                u32 bh4[4], bl4[4];
                ldm_x4t(bh4, sb + PJ_WH + rb);
                ldm_x4t(bl4, sb + PJ_WL + rb);
#pragma unroll
                for (int m = 0; m < 2; m++) {
                    mma_bf16(acc[m][nf*2],   ah[m], bh4[0], bh4[1]);
                    mma_bf16(acc[m][nf*2],   ah[m], bl4[0], bl4[1]);
                    mma_bf16(acc[m][nf*2],   al[m], bh4[0], bh4[1]);
                    mma_bf16(acc[m][nf*2+1], ah[m], bh4[2], bh4[3]);
                    mma_bf16(acc[m][nf*2+1], ah[m], bl4[2], bl4[3]);
                    mma_bf16(acc[m][nf*2+1], al[m], bh4[2], bh4[3]);
                }
            }
        }
    }

    int r0 = m0 + wm * 32 + (lane >> 2);
    int cb = n0 + wn * 64 + (lane & 3) * 2;
#pragma unroll
    for (int m = 0; m < 2; m++) {
#pragma unroll
        for (int j = 0; j < 8; j++) {
            int col = cb + j * 8;
            float2 bv = *(const float2*)&bias[col];
            int rowA = r0 + m * 16, rowB = rowA + 8;
            float2 vA = make_float2(acc[m][j][0] + bv.x, acc[m][j][1] + bv.y);
            float2 vB = make_float2(acc[m][j][2] + bv.x, acc[m][j][3] + bv.y);
            if (permute) {
                int h = col >> 6, dd = col & 63;
                size_t eA = ((size_t)((rowA >> 10) * HH + h) * NQ + (rowA & 1023)) * 64 + dd;
                size_t eB = ((size_t)((rowB >> 10) * HH + h) * NQ + (rowB & 1023)) * 64 + dd;
                u32 hA, lA, hB, lB;
                split2(vA, hA, lA); split2(vB, hB, lB);
                *(u32*)((char*)Ohi + eA * 2) = hA;
                *(u32*)((char*)Olo + eA * 2) = lA;
                *(u32*)((char*)Ohi + eB * 2) = hB;
                *(u32*)((char*)Olo + eB * 2) = lB;
            } else {
                *(float2*)(C + (size_t)rowA * 512 + col) = vA;
                *(float2*)(C + (size_t)rowB * 512 + col) = vB;
            }
        }
    }
}

// =====================================================================
// bias_mma v2: one CTA per q, loop over 8 k-tiles of 128.
// D[k=128][bh=64] = Rtile @ Q^T (3-split). Q frags hoisted. Sb bf16.
// smem: RH 0(18432) RL 18432 QH 36864(9216) QL 46080 -> 55296
// =====================================================================
#define BZ_RH 0
#define BZ_RL 18432
#define BZ_QH 36864
#define BZ_QL 46080
#define BIAS_SMEM 55296

__global__ __launch_bounds__(256) void bias_mma(
    const __nv_bfloat16* __restrict__ Qhh, const __nv_bfloat16* __restrict__ Qhl,
    const float* __restrict__ R, __nv_bfloat16* __restrict__ Sb)
{
    extern __shared__ __align__(128) char smem[];
    u32 sb = smem_u32(smem);
    int tid = threadIdx.x, wid = tid >> 5, lane = tid & 31;
    int wm = wid & 3, wn = wid >> 2;
    int q = blockIdx.x;

    // Q: 64 rows x 64 d bf16 hi/lo -> smem stride 72
#pragma unroll
    for (int r = 0; r < 2; r++) {
        int idx = tid + r * 256;
        int row = idx >> 3, c4 = idx & 7;
        u32 off = (u32)(row * 144 + c4 * 16);
        size_t e = ((size_t)row * NQ + q) * DHD + c4 * 8;
        *(uint4*)(smem + BZ_QH + off) = *(const uint4*)((const char*)Qhh + e * 2);
        *(uint4*)(smem + BZ_QL + off) = *(const uint4*)((const char*)Qhl + e * 2);
    }
    __syncthreads();

    // hoist Q (B-side) frags: ks 0..3, g 0..1
    u32 qh4[4][2][4], ql4[4][2][4];
#pragma unroll
    for (int ks = 0; ks < 4; ks++)
#pragma unroll
        for (int g = 0; g < 2; g++) {
            u32 rb = (u32)((wn * 32 + g * 16 + (lane & 7) + ((lane >> 4) << 3)) * 72
                           + ks * 16 + (((lane >> 3) & 1) << 3)) * 2;
            ldm_x4(qh4[ks][g], sb + BZ_QH + rb);
            ldm_x4(ql4[ks][g], sb + BZ_QL + rb);
        }

    for (int kt = 0; kt < 8; kt++) {
        int k0 = kt * 128;
#pragma unroll
        for (int r = 0; r < 8; r++) {
            int idx = tid + r * 256;
            int row = idx >> 4, col = (idx & 15) << 2;
            float4 v = *(const float4*)(R + ((size_t)q * NKV + k0 + row) * DHD + col);
            ull h8, l8; split4(v, h8, l8);
            *(ull*)(smem + BZ_RH + (row * 72 + col) * 2) = h8;
            *(ull*)(smem + BZ_RL + (row * 72 + col) * 2) = l8;
        }
        __syncthreads();

        float acc[2][4][4];
#pragma unroll
        for (int m = 0; m < 2; m++)
#pragma unroll
            for (int j = 0; j < 4; j++)
#pragma unroll
                for (int t = 0; t < 4; t++) acc[m][j][t] = 0.f;

#pragma unroll
        for (int ks = 0; ks < 4; ks++) {
            u32 ah[2][4], al[2][4];
#pragma unroll
            for (int f = 0; f < 2; f++) {
                u32 ra = (u32)((wm * 32 + f * 16 + (lane & 15)) * 72 + ks * 16 + ((lane >> 4) << 3)) * 2;
                ldm_x4(ah[f], sb + BZ_RH + ra);
                ldm_x4(al[f], sb + BZ_RL + ra);
            }
#pragma unroll
            for (int g = 0; g < 2; g++)
#pragma unroll
                for (int m = 0; m < 2; m++) {
                    mma_bf16(acc[m][g*2],   ah[m], qh4[ks][g][0], qh4[ks][g][1]);
                    mma_bf16(acc[m][g*2],   ah[m], ql4[ks][g][0], ql4[ks][g][1]);
                    mma_bf16(acc[m][g*2],   al[m], qh4[ks][g][0], qh4[ks][g][1]);
                    mma_bf16(acc[m][g*2+1], ah[m], qh4[ks][g][2], qh4[ks][g][3]);
                    mma_bf16(acc[m][g*2+1], ah[m], ql4[ks][g][2], ql4[ks][g][3]);
                    mma_bf16(acc[m][g*2+1], al[m], qh4[ks][g][2], qh4[ks][g][3]);
                }
        }
        __syncthreads();   // done reading R region; reuse as T

        float* T = (float*)smem;   // [bh][k] stride 132
#pragma unroll
        for (int m = 0; m < 2; m++) {
            int krow = wm * 32 + m * 16 + (lane >> 2);
#pragma unroll
            for (int j = 0; j < 4; j++) {
                int bhc = wn * 32 + j * 8 + (lane & 3) * 2;
                T[bhc * 132 + krow]           = acc[m][j][0];
                T[(bhc + 1) * 132 + krow]     = acc[m][j][1];
                T[bhc * 132 + krow + 8]       = acc[m][j][2];
                T[(bhc + 1) * 132 + krow + 8] = acc[m][j][3];
            }
        }
        __syncthreads();

        int bh2 = tid >> 2, part = tid & 3;
        size_t dbase = ((size_t)q * BHN + bh2) * NKV + k0 + part * 32;
#pragma unroll
        for (int j = 0; j < 4; j++) {
            float4 a = *(float4*)&T[bh2 * 132 + part * 32 + j * 8];
            float4 b = *(float4*)&T[bh2 * 132 + part * 32 + j * 8 + 4];
            uint4 o;
            o.x = pkbf(a.x, a.y); o.y = pkbf(a.z, a.w);
            o.z = pkbf(b.x, b.y); o.w = pkbf(b.z, b.w);
            *(uint4*)((char*)Sb + (dbase + j * 8) * 2) = o;
        }
        __syncthreads();   // before next R load overwrites T
    }
}

// =====================================================================
// attn_mma: CTA per (bh, 32-q tile). cp.async double-buffered K/V
// chunks of 128 rows, direct bf16 hi/lo loads, Sb bf16.
// =====================================================================
#define SROW  1028
#define AS_MB 131584
#define AS_QH 135680
#define AS_QL 140288
#define AS_KB 144896
#define KBUF  36864
#define KLO   18432
#define ATTN_SMEM 218624

__global__ __launch_bounds__(256) void attn_mma(
    const __nv_bfloat16* __restrict__ Qhh, const __nv_bfloat16* __restrict__ Qhl,
    const __nv_bfloat16* __restrict__ Khh, const __nv_bfloat16* __restrict__ Khl,
    const __nv_bfloat16* __restrict__ Vhh, const __nv_bfloat16* __restrict__ Vhl,
    const __nv_bfloat16* __restrict__ Sb,
    const int* __restrict__ mask, float* __restrict__ attn,
    float* __restrict__ ctx)
{
    extern __shared__ __align__(128) char smem[];
    u32 sbp = smem_u32(smem);
    float* S  = (float*)smem;
    float* mb = (float*)(smem + AS_MB);
    int tid = threadIdx.x, wid = tid >> 5, lane = tid & 31;
    int bh  = blockIdx.x;
    int q0  = blockIdx.y * 32;
    int b = bh >> 3, h = bh & 7;
    const float scale = 0.125f;

    const __nv_bfloat16* KhB = Khh + (size_t)bh * NKV * DHD;
    const __nv_bfloat16* KlB = Khl + (size_t)bh * NKV * DHD;
    const __nv_bfloat16* VhB = Vhh + (size_t)bh * NKV * DHD;
    const __nv_bfloat16* VlB = Vhl + (size_t)bh * NKV * DHD;

    // Q tile: 32 rows x 8 u4, one u4 per thread per array
    {
        int row = tid >> 3, c4 = tid & 7;
        u32 off = (u32)(row * 144 + c4 * 16);
        size_t e = ((size_t)bh * NQ + q0 + row) * DHD + c4 * 8;
        *(uint4*)(smem + AS_QH + off) = *(const uint4*)((const char*)Qhh + e * 2);
        *(uint4*)(smem + AS_QL + off) = *(const uint4*)((const char*)Qhl + e * 2);
    }
    for (int k = tid; k < NKV; k += 256)
        mb[k] = mask[b * NKV + k] ? 0.f : -1e30f;
    __syncthreads();

    // hoist Q fragments: 4 d-steps x 2 m
    u32 qh[4][2][4], ql[4][2][4];
#pragma unroll
    for (int ds = 0; ds < 4; ds++)
#pragma unroll
        for (int m = 0; m < 2; m++) {
            u32 ra = (u32)((m * 16 + (lane & 15)) * 72 + ds * 16 + ((lane >> 4) << 3)) * 2;
            ldm_x4(qh[ds][m], sbp + AS_QH + ra);
            ldm_x4(ql[ds][m], sbp + AS_QL + ra);
        }

    int prow = tid >> 3, pc4 = tid & 7;   // chunk-copy mapping: 4 iters cover 128x8
    u32 poff0 = (u32)(prow * 144 + pc4 * 16);
    size_t psrc0 = (size_t)prow * 64 + pc4 * 8;

#define ISSUE_CHUNK(HIptr, LOptr, cix, buf) do {                                   \
        u32 dh_ = sbp + AS_KB + (buf) * KBUF;                                      \
        u32 dl_ = dh_ + KLO;                                                       \
        const char* sh_ = (const char*)((HIptr) + (size_t)(cix) * 128 * 64);       \
        const char* sl_ = (const char*)((LOptr) + (size_t)(cix) * 128 * 64);       \
        _Pragma("unroll")                                                          \
        for (int r_ = 0; r_ < 4; r_++) {                                           \
            u32 o_ = poff0 + (u32)r_ * 32 * 144;                                   \
            size_t s_ = (psrc0 + (size_t)r_ * 32 * 64) * 2;                        \
            CP_ASYNC16(dh_ + o_, sh_ + s_);                                        \
            CP_ASYNC16(dl_ + o_, sl_ + s_);                                        \
        }                                                                          \
        CP_COMMIT();                                                               \
    } while (0)

    // ---- Phase 1: QK^T + Sb + mask, 8 chunks of 128 k ----
    ISSUE_CHUNK(KhB, KlB, 0, 0);
    for (int c = 0; c < 8; c++) {
        if (c < 7) { ISSUE_CHUNK(KhB, KlB, c + 1, (c + 1) & 1); CP_WAIT1(); }
        else CP_WAIT0();
        __syncthreads();

        u32 bufH = sbp + AS_KB + (c & 1) * KBUF;
        u32 bufL = bufH + KLO;

        float acc[2][2][4];
#pragma unroll
        for (int m = 0; m < 2; m++)
#pragma unroll
            for (int j = 0; j < 2; j++)
#pragma unroll
                for (int t = 0; t < 4; t++) acc[m][j][t] = 0.f;

#pragma unroll
        for (int ds = 0; ds < 4; ds++) {
            u32 rb = (u32)((wid * 16 + (lane & 15)) * 72 + ds * 16 + ((lane >> 4) << 3)) * 2;
            u32 kh4[4], kl4[4];
            ldm_x4(kh4, bufH + rb);
            ldm_x4(kl4, bufL + rb);
#pragma unroll
            for (int m = 0; m < 2; m++) {
                mma_bf16(acc[m][0], qh[ds][m], kh4[0], kh4[2]);
                mma_bf16(acc[m][0], qh[ds][m], kl4[0], kl4[2]);
                mma_bf16(acc[m][0], ql[ds][m], kh4[0], kh4[2]);
                mma_bf16(acc[m][1], qh[ds][m], kh4[1], kh4[3]);
                mma_bf16(acc[m][1], qh[ds][m], kl4[1], kl4[3]);
                mma_bf16(acc[m][1], ql[ds][m], kh4[1], kh4[3]);
            }
        }
        // epilogue: S = (acc + Sb)*scale + mask  (Sb bf16)
#pragma unroll
        for (int m = 0; m < 2; m++) {
            int qq = m * 16 + (lane >> 2);
#pragma unroll
            for (int j = 0; j < 2; j++) {
                int k = c * 128 + wid * 16 + j * 8 + (lane & 3) * 2;
                u32 u0 = *(const u32*)((const char*)Sb + (((size_t)(q0 + qq) * BHN + bh) * NKV + k) * 2);
                u32 u1 = *(const u32*)((const char*)Sb + (((size_t)(q0 + qq + 8) * BHN + bh) * NKV + k) * 2);
                float2 b0 = __bfloat1622float2(*(__nv_bfloat162*)&u0);
                float2 b1 = __bfloat1622float2(*(__nv_bfloat162*)&u1);
                float2 mm = *(const float2*)&mb[k];
                *(float2*)&S[qq * SROW + k] = make_float2(
                    (acc[m][j][0] + b0.x) * scale + mm.x,
                    (acc[m][j][1] + b0.y) * scale + mm.y);
                *(float2*)&S[(qq + 8) * SROW + k] = make_float2(
                    (acc[m][j][2] + b1.x) * scale + mm.x,
                    (acc[m][j][3] + b1.y) * scale + mm.y);
            }
        }
        __syncthreads();
    }

    // ---- Phase 2: softmax + attn store ----
    for (int r = 0; r < 4; r++) {
        float* row = S + (wid * 4 + r) * SROW;
        float m = -3.4e38f;
        for (int k = lane; k < NKV; k += 32) m = fmaxf(m, row[k]);
#pragma unroll
        for (int o = 16; o; o >>= 1) m = fmaxf(m, __shfl_xor_sync(0xffffffffu, m, o));
        float s = 0.f;
        for (int k = lane; k < NKV; k += 32) {
            float e = __expf(row[k] - m);
            row[k] = e; s += e;
        }
#pragma unroll
        for (int o = 16; o; o >>= 1) s += __shfl_xor_sync(0xffffffffu, s, o);
        float inv = 1.f / s;
        __syncwarp();
        float* arow = attn + ((size_t)bh * NQ + q0 + wid * 4 + r) * NKV;
        for (int k = lane * 4; k < NKV; k += 128) {
            float4 v = *(float4*)&row[k];
            v.x *= inv; v.y *= inv; v.z *= inv; v.w *= inv;
            *(float4*)&row[k] = v;
            *(float4*)&arow[k] = v;
        }
        __syncwarp();
    }
    __syncthreads();

    // ---- Phase 3: ctx = P @ V, 8 chunks of 128 k ----
    float acc[2][8][4];
#pragma unroll
    for (int m = 0; m < 2; m++)
#pragma unroll
        for (int j = 0; j < 8; j++)
#pragma unroll
            for (int t = 0; t < 4; t++) acc[m][j][t] = 0.f;

    ISSUE_CHUNK(VhB, VlB, 0, 0);
    for (int c = 0; c < 8; c++) {
        if (c < 7) { ISSUE_CHUNK(VhB, VlB, c + 1, (c + 1) & 1); CP_WAIT1(); }
        else CP_WAIT0();
        __syncthreads();

        u32 bufH = sbp + AS_KB + (c & 1) * KBUF;
        u32 bufL = bufH + KLO;
        int kbase = c * 128 + wid * 16;

        u32 ph[2][4], pl[2][4];
#pragma unroll
        for (int m = 0; m < 2; m++) {
            int r0 = m * 16 + (lane >> 2);
            const float* Sr0 = S + r0 * SROW;
            const float* Sr1 = S + (r0 + 8) * SROW;
            int cc = kbase + (lane & 3) * 2;
            split2(*(const float2*)(Sr0 + cc),     ph[m][0], pl[m][0]);
            split2(*(const float2*)(Sr1 + cc),     ph[m][1], pl[m][1]);
            split2(*(const float2*)(Sr0 + cc + 8), ph[m][2], pl[m][2]);
            split2(*(const float2*)(Sr1 + cc + 8), ph[m][3], pl[m][3]);
        }
#pragma unroll
        for (int dn = 0; dn < 4; dn++) {
            u32 rv = (u32)((wid * 16 + (lane & 15)) * 72 + dn * 16 + ((lane >> 4) << 3)) * 2;
            u32 vh4[4], vl4[4];
            ldm_x4t(vh4, bufH + rv);
            ldm_x4t(vl4, bufL + rv);
#pragma unroll
            for (int m = 0; m < 2; m++) {
                mma_bf16(acc[m][dn*2],   ph[m], vh4[0], vh4[1]);
                mma_bf16(acc[m][dn*2],   ph[m], vl4[0], vl4[1]);
                mma_bf16(acc[m][dn*2],   pl[m], vh4[0], vh4[1]);
                mma_bf16(acc[m][dn*2+1], ph[m], vh4[2], vh4[3]);
                mma_bf16(acc[m][dn*2+1], ph[m], vl4[2], vl4[3]);
                mma_bf16(acc[m][dn*2+1], pl[m], vh4[2], vh4[3]);
            }
        }
        __syncthreads();
    }

    // slab reduce over 8 warps: slab[w][q][d], stride 68
    float* slab = (float*)(smem + AS_KB);
#pragma unroll
    for (int m = 0; m < 2; m++) {
        int qq = m * 16 + (lane >> 2);
#pragma unroll
        for (int j = 0; j < 8; j++) {
            int d = j * 8 + (lane & 3) * 2;
            *(float2*)&slab[(wid * 32 + qq) * 68 + d]     = make_float2(acc[m][j][0], acc[m][j][1]);
            *(float2*)&slab[(wid * 32 + qq + 8) * 68 + d] = make_float2(acc[m][j][2], acc[m][j][3]);
        }
    }
    __syncthreads();

    {
        int qq = tid >> 3, db = (tid & 7) * 8;
        float s[8];
#pragma unroll
        for (int t = 0; t < 8; t++) s[t] = 0.f;
#pragma unroll
        for (int w = 0; w < 8; w++) {
            const float* p = &slab[(w * 32 + qq) * 68 + db];
#pragma unroll
            for (int t = 0; t < 8; t++) s[t] += p[t];
        }
        float* dst = ctx + ((size_t)b * NQ + q0 + qq) * DM + h * DHD + db;
#pragma unroll
        for (int t = 0; t < 8; t += 4)
            *(float4*)(dst + t) = make_float4(s[t], s[t+1], s[t+2], s[t+3]);
    }
}

// =====================================================================
// launcher
// =====================================================================
extern "C" void kernel_launch(void* const* d_in, const int* in_sizes, int n_in,
                              void* d_out, int out_size)
{
    const float* q    = (const float*)d_in[0];
    const float* kv   = (const float*)d_in[1];
    const int*   mask = (const int*)  d_in[2];
    const float* Wq   = (const float*)d_in[3];
    const float* bq   = (const float*)d_in[4];
    const float* Wk   = (const float*)d_in[5];
    const float* bk   = (const float*)d_in[6];
    const float* Wv   = (const float*)d_in[7];
    const float* bv   = (const float*)d_in[8];
    const float* Wo   = (const float*)d_in[9];
    const float* bo   = (const float*)d_in[10];
    const float* R    = (const float*)d_in[11];

    float* out = (float*)d_out;
    const size_t out_elems  = (size_t)BB*NQ*DM;
    const size_t attn_elems = (size_t)BHN*NQ*NKV;

    __nv_bfloat16 *Qhh, *Qhl, *Khh, *Khl, *Vhh, *Vhl, *Sb;
    float *ctx, *attn_fb;
    cudaGetSymbolAddress((void**)&Qhh, g_Qhh);
    cudaGetSymbolAddress((void**)&Qhl, g_Qhl);
    cudaGetSymbolAddress((void**)&Khh, g_Khh);
    cudaGetSymbolAddress((void**)&Khl, g_Khl);
    cudaGetSymbolAddress((void**)&Vhh, g_Vhh);
    cudaGetSymbolAddress((void**)&Vhl, g_Vhl);
    cudaGetSymbolAddress((void**)&Sb,  g_Sb);
    cudaGetSymbolAddress((void**)&ctx, g_ctx);
    cudaGetSymbolAddress((void**)&attn_fb, g_attn_fallback);

    float* attn = ((size_t)out_size >= out_elems + attn_elems)
                ? (out + out_elems) : attn_fb;

    cudaFuncSetAttribute(proj_mma, cudaFuncAttributeMaxDynamicSharedMemorySize, PROJ_SMEM);
    cudaFuncSetAttribute(bias_mma, cudaFuncAttributeMaxDynamicSharedMemorySize, BIAS_SMEM);
    cudaFuncSetAttribute(attn_mma, cudaFuncAttributeMaxDynamicSharedMemorySize, ATTN_SMEM);

    dim3 gProj(4, 64);
    proj_mma<<<gProj, 256, PROJ_SMEM>>>(q,  Wq, bq, nullptr, Qhh, Qhl, 1);
    proj_mma<<<gProj, 256, PROJ_SMEM>>>(kv, Wk, bk, nullptr, Khh, Khl, 1);
    proj_mma<<<gProj, 256, PROJ_SMEM>>>(kv, Wv, bv, nullptr, Vhh, Vhl, 1);

    bias_mma<<<1024, 256, BIAS_SMEM>>>(Qhh, Qhl, R, Sb);

    attn_mma<<<dim3(64, 32), 256, ATTN_SMEM>>>(Qhh, Qhl, Khh, Khl, Vhh, Vhl,
                                               Sb, mask, attn, ctx);

    proj_mma<<<gProj, 256, PROJ_SMEM>>>(ctx, Wo, bo, out, nullptr, nullptr, 0);
}

// round 10
// speedup vs baseline: 2.2788x; 1.0539x over previous
#include <cuda_runtime.h>
#include <cuda_bf16.h>
#include <cstdint>
#include <cstddef>

#define BB    8
#define HH    8
#define NQ    1024
#define NKV   1024
#define DHD   64
#define DM    512
#define BHN   (BB*HH)

typedef unsigned long long ull;
typedef uint32_t u32;

__device__ __forceinline__ u32 smem_u32(const void* p) {
    u32 a;
    asm("{ .reg .u64 t; cvta.to.shared.u64 t, %1; cvt.u32.u64 %0, t; }" : "=r"(a) : "l"(p));
    return a;
}
__device__ __forceinline__ void ldm_x4(u32* r, u32 a) {
    asm volatile("ldmatrix.sync.aligned.m8n8.x4.shared.b16 {%0,%1,%2,%3}, [%4];"
        : "=r"(r[0]),"=r"(r[1]),"=r"(r[2]),"=r"(r[3]) : "r"(a));
}
__device__ __forceinline__ void ldm_x4t(u32* r, u32 a) {
    asm volatile("ldmatrix.sync.aligned.m8n8.x4.trans.shared.b16 {%0,%1,%2,%3}, [%4];"
        : "=r"(r[0]),"=r"(r[1]),"=r"(r[2]),"=r"(r[3]) : "r"(a));
}
__device__ __forceinline__ void mma_bf16(float* c, const u32* a, u32 b0, u32 b1) {
    asm volatile("mma.sync.aligned.m16n8k16.row.col.f32.bf16.bf16.f32 "
        "{%0,%1,%2,%3}, {%4,%5,%6,%7}, {%8,%9}, {%0,%1,%2,%3};"
        : "+f"(c[0]),"+f"(c[1]),"+f"(c[2]),"+f"(c[3])
        : "r"(a[0]),"r"(a[1]),"r"(a[2]),"r"(a[3]), "r"(b0),"r"(b1));
}
__device__ __forceinline__ void split4(float4 v, ull& hi8, ull& lo8) {
    __nv_bfloat162 h01 = __floats2bfloat162_rn(v.x, v.y);
    __nv_bfloat162 h23 = __floats2bfloat162_rn(v.z, v.w);
    float2 f01 = __bfloat1622float2(h01);
    float2 f23 = __bfloat1622float2(h23);
    __nv_bfloat162 l01 = __floats2bfloat162_rn(v.x - f01.x, v.y - f01.y);
    __nv_bfloat162 l23 = __floats2bfloat162_rn(v.z - f23.x, v.w - f23.y);
    u32 uh0 = *(u32*)&h01, uh1 = *(u32*)&h23;
    u32 ul0 = *(u32*)&l01, ul1 = *(u32*)&l23;
    hi8 = (ull)uh0 | ((ull)uh1 << 32);
    lo8 = (ull)ul0 | ((ull)ul1 << 32);
}
__device__ __forceinline__ void split2(float2 v, u32& h, u32& l) {
    __nv_bfloat162 hb = __floats2bfloat162_rn(v.x, v.y);
    float2 hf = __bfloat1622float2(hb);
    __nv_bfloat162 lb = __floats2bfloat162_rn(v.x - hf.x, v.y - hf.y);
    h = *(u32*)&hb; l = *(u32*)&lb;
}
__device__ __forceinline__ u32 pkbf(float x, float y) {
    __nv_bfloat162 t = __floats2bfloat162_rn(x, y);
    return *(u32*)&t;
}

#define CP_ASYNC16(dst, src) \
    asm volatile("cp.async.ca.shared.global [%0], [%1], 16;" :: "r"(dst), "l"(src) : "memory")
#define CP_COMMIT() asm volatile("cp.async.commit_group;" ::: "memory")
#define CP_WAIT0()  asm volatile("cp.async.wait_group 0;" ::: "memory")

// ---------------- device scratch ----------------
__device__ __nv_bfloat16 g_Qhh[(size_t)BHN*NQ*DHD];
__device__ __nv_bfloat16 g_Qhl[(size_t)BHN*NQ*DHD];
__device__ __nv_bfloat16 g_Khh[(size_t)BHN*NKV*DHD];
__device__ __nv_bfloat16 g_Khl[(size_t)BHN*NKV*DHD];
__device__ __nv_bfloat16 g_Vhh[(size_t)BHN*NKV*DHD];
__device__ __nv_bfloat16 g_Vhl[(size_t)BHN*NKV*DHD];
__device__ __nv_bfloat16 g_Sb[(size_t)NQ*BHN*NKV];
__device__ float g_ctx[(size_t)BB*NQ*DM];
__device__ float g_attn_fallback[(size_t)BHN*NQ*NKV];

// =====================================================================
// proj_mma: unchanged (round-9, passing).
// =====================================================================
#define PJ_AH 0
#define PJ_AL 10240
#define PJ_WH 20480
#define PJ_WL 29184
#define PROJ_SMEM 37888

__global__ __launch_bounds__(256) void proj_mma(
    const float* __restrict__ A, const float* __restrict__ W,
    const float* __restrict__ bias, float* __restrict__ C,
    __nv_bfloat16* __restrict__ Ohi, __nv_bfloat16* __restrict__ Olo,
    int permute)
{
    extern __shared__ __align__(128) char smem[];
    u32 sb = smem_u32(smem);
    int tid = threadIdx.x, wid = tid >> 5, lane = tid & 31;
    int m0 = blockIdx.y * 128, n0 = blockIdx.x * 128;
    int wm = wid & 3, wn = wid >> 2;

    float acc[2][8][4];
#pragma unroll
    for (int m = 0; m < 2; m++)
#pragma unroll
        for (int j = 0; j < 8; j++)
#pragma unroll
            for (int t = 0; t < 4; t++) acc[m][j][t] = 0.f;

    float4 pa[4], pw[4];
#pragma unroll
    for (int r = 0; r < 4; r++) {
        int idx = tid + r * 256;
        pa[r] = *(const float4*)(A + (size_t)(m0 + (idx >> 3)) * 512 + ((idx & 7) << 2));
        pw[r] = *(const float4*)(W + (size_t)(idx >> 5) * 512 + n0 + ((idx & 31) << 2));
    }

    for (int kb = 0; kb < 16; kb++) {
        if (kb) __syncthreads();
#pragma unroll
        for (int r = 0; r < 4; r++) {
            int idx = tid + r * 256;
            {
                int row = idx >> 3, col = (idx & 7) << 2;
                ull h8, l8; split4(pa[r], h8, l8);
                *(ull*)(smem + PJ_AH + (row * 40 + col) * 2) = h8;
                *(ull*)(smem + PJ_AL + (row * 40 + col) * 2) = l8;
            }
            {
                int row = idx >> 5, col = (idx & 31) << 2;
                ull h8, l8; split4(pw[r], h8, l8);
                *(ull*)(smem + PJ_WH + (row * 136 + col) * 2) = h8;
                *(ull*)(smem + PJ_WL + (row * 136 + col) * 2) = l8;
            }
        }
        __syncthreads();
        if (kb < 15) {
            int k0 = (kb + 1) * 32;
#pragma unroll
            for (int r = 0; r < 4; r++) {
                int idx = tid + r * 256;
                pa[r] = *(const float4*)(A + (size_t)(m0 + (idx >> 3)) * 512 + k0 + ((idx & 7) << 2));
                pw[r] = *(const float4*)(W + (size_t)(k0 + (idx >> 5)) * 512 + n0 + ((idx & 31) << 2));
            }
        }
#pragma unroll
        for (int ks = 0; ks < 32; ks += 16) {
            u32 ah[2][4], al[2][4];
#pragma unroll
            for (int f = 0; f < 2; f++) {
                u32 ra = (u32)((wm * 32 + f * 16 + (lane & 15)) * 40 + ks + ((lane >> 4) << 3)) * 2;
                ldm_x4(ah[f], sb + PJ_AH + ra);
                ldm_x4(al[f], sb + PJ_AL + ra);
            }
#pragma unroll
            for (int nf = 0; nf < 4; nf++) {
                u32 rb = (u32)((ks + (lane & 15)) * 136 + wn * 64 + nf * 16 + ((lane >> 4) << 3)) * 2;
                u32 bh4[4], bl4[4];
                ldm_x4t(bh4, sb + PJ_WH + rb);
                ldm_x4t(bl4, sb + PJ_WL + rb);
#pragma unroll
                for (int m = 0; m < 2; m++) {
                    mma_bf16(acc[m][nf*2],   ah[m], bh4[0], bh4[1]);
                    mma_bf16(acc[m][nf*2],   ah[m], bl4[0], bl4[1]);
                    mma_bf16(acc[m][nf*2],   al[m], bh4[0], bh4[1]);
                    mma_bf16(acc[m][nf*2+1], ah[m], bh4[2], bh4[3]);
                    mma_bf16(acc[m][nf*2+1], ah[m], bl4[2], bl4[3]);
                    mma_bf16(acc[m][nf*2+1], al[m], bh4[2], bh4[3]);
                }
            }
        }
    }

    int r0 = m0 + wm * 32 + (lane >> 2);
    int cb = n0 + wn * 64 + (lane & 3) * 2;
#pragma unroll
    for (int m = 0; m < 2; m++) {
#pragma unroll
        for (int j = 0; j < 8; j++) {
            int col = cb + j * 8;
            float2 bv = *(const float2*)&bias[col];
            int rowA = r0 + m * 16, rowB = rowA + 8;
            float2 vA = make_float2(acc[m][j][0] + bv.x, acc[m][j][1] + bv.y);
            float2 vB = make_float2(acc[m][j][2] + bv.x, acc[m][j][3] + bv.y);
            if (permute) {
                int h = col >> 6, dd = col & 63;
                size_t eA = ((size_t)((rowA >> 10) * HH + h) * NQ + (rowA & 1023)) * 64 + dd;
                size_t eB = ((size_t)((rowB >> 10) * HH + h) * NQ + (rowB & 1023)) * 64 + dd;
                u32 hA, lA, hB, lB;
                split2(vA, hA, lA); split2(vB, hB, lB);
                *(u32*)((char*)Ohi + eA * 2) = hA;
                *(u32*)((char*)Olo + eA * 2) = lA;
                *(u32*)((char*)Ohi + eB * 2) = hB;
                *(u32*)((char*)Olo + eB * 2) = lB;
            } else {
                *(float2*)(C + (size_t)rowA * 512 + col) = vA;
                *(float2*)(C + (size_t)rowB * 512 + col) = vB;
            }
        }
    }
}

// =====================================================================
// bias_mma v3: 2-term (R quantized to bf16 once — Sb storage is bf16
// anyway). grid (2, 1024): CTA (kc, q) does 4 k-tiles of 128.
// =====================================================================
#define BZ_RH 0
#define BZ_QH 36864
#define BZ_QL 46080
#define BIAS_SMEM 55296

__global__ __launch_bounds__(256) void bias_mma(
    const __nv_bfloat16* __restrict__ Qhh, const __nv_bfloat16* __restrict__ Qhl,
    const float* __restrict__ R, __nv_bfloat16* __restrict__ Sb)
{
    extern __shared__ __align__(128) char smem[];
    u32 sb = smem_u32(smem);
    int tid = threadIdx.x, wid = tid >> 5, lane = tid & 31;
    int wm = wid & 3, wn = wid >> 2;
    int q = blockIdx.y, kc = blockIdx.x;

#pragma unroll
    for (int r = 0; r < 2; r++) {
        int idx = tid + r * 256;
        int row = idx >> 3, c4 = idx & 7;
        u32 off = (u32)(row * 144 + c4 * 16);
        size_t e = ((size_t)row * NQ + q) * DHD + c4 * 8;
        *(uint4*)(smem + BZ_QH + off) = *(const uint4*)((const char*)Qhh + e * 2);
        *(uint4*)(smem + BZ_QL + off) = *(const uint4*)((const char*)Qhl + e * 2);
    }
    __syncthreads();

    u32 qh4[4][2][4], ql4[4][2][4];
#pragma unroll
    for (int ks = 0; ks < 4; ks++)
#pragma unroll
        for (int g = 0; g < 2; g++) {
            u32 rb = (u32)((wn * 32 + g * 16 + (lane & 7) + ((lane >> 4) << 3)) * 72
                           + ks * 16 + (((lane >> 3) & 1) << 3)) * 2;
            ldm_x4(qh4[ks][g], sb + BZ_QH + rb);
            ldm_x4(ql4[ks][g], sb + BZ_QL + rb);
        }

    for (int kt = 0; kt < 4; kt++) {
        int k0 = (kc * 4 + kt) * 128;
#pragma unroll
        for (int r = 0; r < 8; r++) {
            int idx = tid + r * 256;
            int row = idx >> 4, col = (idx & 15) << 2;
            float4 v = *(const float4*)(R + ((size_t)q * NKV + k0 + row) * DHD + col);
            u32 p0 = pkbf(v.x, v.y), p1 = pkbf(v.z, v.w);
            *(ull*)(smem + BZ_RH + (row * 72 + col) * 2) = (ull)p0 | ((ull)p1 << 32);
        }
        __syncthreads();

        float acc[2][4][4];
#pragma unroll
        for (int m = 0; m < 2; m++)
#pragma unroll
            for (int j = 0; j < 4; j++)
#pragma unroll
                for (int t = 0; t < 4; t++) acc[m][j][t] = 0.f;

#pragma unroll
        for (int ks = 0; ks < 4; ks++) {
            u32 ah[2][4];
#pragma unroll
            for (int f = 0; f < 2; f++) {
                u32 ra = (u32)((wm * 32 + f * 16 + (lane & 15)) * 72 + ks * 16 + ((lane >> 4) << 3)) * 2;
                ldm_x4(ah[f], sb + BZ_RH + ra);
            }
#pragma unroll
            for (int g = 0; g < 2; g++)
#pragma unroll
                for (int m = 0; m < 2; m++) {
                    mma_bf16(acc[m][g*2],   ah[m], qh4[ks][g][0], qh4[ks][g][1]);
                    mma_bf16(acc[m][g*2],   ah[m], ql4[ks][g][0], ql4[ks][g][1]);
                    mma_bf16(acc[m][g*2+1], ah[m], qh4[ks][g][2], qh4[ks][g][3]);
                    mma_bf16(acc[m][g*2+1], ah[m], ql4[ks][g][2], ql4[ks][g][3]);
                }
        }
        __syncthreads();

        float* T = (float*)smem;   // [bh][k] stride 132, fits below BZ_QH
#pragma unroll
        for (int m = 0; m < 2; m++) {
            int krow = wm * 32 + m * 16 + (lane >> 2);
#pragma unroll
            for (int j = 0; j < 4; j++) {
                int bhc = wn * 32 + j * 8 + (lane & 3) * 2;
                T[bhc * 132 + krow]           = acc[m][j][0];
                T[(bhc + 1) * 132 + krow]     = acc[m][j][1];
                T[bhc * 132 + krow + 8]       = acc[m][j][2];
                T[(bhc + 1) * 132 + krow + 8] = acc[m][j][3];
            }
        }
        __syncthreads();

        int bh2 = tid >> 2, part = tid & 3;
        size_t dbase = ((size_t)q * BHN + bh2) * NKV + k0 + part * 32;
#pragma unroll
        for (int j = 0; j < 4; j++) {
            float4 a = *(float4*)&T[bh2 * 132 + part * 32 + j * 8];
            float4 b = *(float4*)&T[bh2 * 132 + part * 32 + j * 8 + 4];
            uint4 o;
            o.x = pkbf(a.x, a.y); o.y = pkbf(a.z, a.w);
            o.z = pkbf(b.x, b.y); o.w = pkbf(b.z, b.w);
            *(uint4*)((char*)Sb + (dbase + j * 8) * 2) = o;
        }
        __syncthreads();
    }
}

// =====================================================================
// attn_mma v2: q-tile 16, 2 CTAs/SM. Single cp.async K/V buffer
// (cross-CTA overlap). grid (64, 64).
// smem: S 0(65792) mb 65792(4096) QH 69888 QL 72192 KB 74496(36864)
// =====================================================================
#define SROW  1028
#define AS_MB 65792
#define AS_QH 69888
#define AS_QL 72192
#define AS_KB 74496
#define KLO   18432
#define ATTN_SMEM 111360

__global__ __launch_bounds__(256, 2) void attn_mma(
    const __nv_bfloat16* __restrict__ Qhh, const __nv_bfloat16* __restrict__ Qhl,
    const __nv_bfloat16* __restrict__ Khh, const __nv_bfloat16* __restrict__ Khl,
    const __nv_bfloat16* __restrict__ Vhh, const __nv_bfloat16* __restrict__ Vhl,
    const __nv_bfloat16* __restrict__ Sb,
    const int* __restrict__ mask, float* __restrict__ attn,
    float* __restrict__ ctx)
{
    extern __shared__ __align__(128) char smem[];
    u32 sbp = smem_u32(smem);
    float* S  = (float*)smem;
    float* mb = (float*)(smem + AS_MB);
    int tid = threadIdx.x, wid = tid >> 5, lane = tid & 31;
    int bh  = blockIdx.x;
    int q0  = blockIdx.y * 16;
    int b = bh >> 3, h = bh & 7;
    const float scale = 0.125f;

    const __nv_bfloat16* KhB = Khh + (size_t)bh * NKV * DHD;
    const __nv_bfloat16* KlB = Khl + (size_t)bh * NKV * DHD;
    const __nv_bfloat16* VhB = Vhh + (size_t)bh * NKV * DHD;
    const __nv_bfloat16* VlB = Vhl + (size_t)bh * NKV * DHD;

    if (tid < 128) {
        int row = tid >> 3, c4 = tid & 7;
        u32 off = (u32)(row * 144 + c4 * 16);
        size_t e = ((size_t)bh * NQ + q0 + row) * DHD + c4 * 8;
        *(uint4*)(smem + AS_QH + off) = *(const uint4*)((const char*)Qhh + e * 2);
        *(uint4*)(smem + AS_QL + off) = *(const uint4*)((const char*)Qhl + e * 2);
    }
    for (int k = tid; k < NKV; k += 256)
        mb[k] = mask[b * NKV + k] ? 0.f : -1e30f;
    __syncthreads();

    u32 qh[4][4], ql[4][4];
#pragma unroll
    for (int ds = 0; ds < 4; ds++) {
        u32 ra = (u32)((lane & 15) * 72 + ds * 16 + ((lane >> 4) << 3)) * 2;
        ldm_x4(qh[ds], sbp + AS_QH + ra);
        ldm_x4(ql[ds], sbp + AS_QL + ra);
    }

    int prow = tid >> 3, pc4 = tid & 7;
    u32 poff0 = (u32)(prow * 144 + pc4 * 16);
    size_t psrc0 = (size_t)prow * 64 + pc4 * 8;

#define ISSUE_CHUNK(HIptr, LOptr, cix) do {                                        \
        u32 dh_ = sbp + AS_KB;                                                     \
        u32 dl_ = dh_ + KLO;                                                       \
        const char* sh_ = (const char*)((HIptr) + (size_t)(cix) * 128 * 64);       \
        const char* sl_ = (const char*)((LOptr) + (size_t)(cix) * 128 * 64);       \
        _Pragma("unroll")                                                          \
        for (int r_ = 0; r_ < 4; r_++) {                                           \
            u32 o_ = poff0 + (u32)r_ * 32 * 144;                                   \
            size_t s_ = (psrc0 + (size_t)r_ * 32 * 64) * 2;                        \
            CP_ASYNC16(dh_ + o_, sh_ + s_);                                        \
            CP_ASYNC16(dl_ + o_, sl_ + s_);                                        \
        }                                                                          \
        CP_COMMIT();                                                               \
    } while (0)

    // ---- Phase 1: QK^T + Sb + mask, 8 chunks of 128 k ----
    for (int c = 0; c < 8; c++) {
        ISSUE_CHUNK(KhB, KlB, c);
        CP_WAIT0();
        __syncthreads();
        u32 bufH = sbp + AS_KB, bufL = bufH + KLO;

        float acc[2][4];
#pragma unroll
        for (int j = 0; j < 2; j++)
#pragma unroll
            for (int t = 0; t < 4; t++) acc[j][t] = 0.f;

#pragma unroll
        for (int ds = 0; ds < 4; ds++) {
            u32 rb = (u32)((wid * 16 + (lane & 15)) * 72 + ds * 16 + ((lane >> 4) << 3)) * 2;
            u32 kh4[4], kl4[4];
            ldm_x4(kh4, bufH + rb);
            ldm_x4(kl4, bufL + rb);
            mma_bf16(acc[0], qh[ds], kh4[0], kh4[2]);
            mma_bf16(acc[0], qh[ds], kl4[0], kl4[2]);
            mma_bf16(acc[0], ql[ds], kh4[0], kh4[2]);
            mma_bf16(acc[1], qh[ds], kh4[1], kh4[3]);
            mma_bf16(acc[1], qh[ds], kl4[1], kl4[3]);
            mma_bf16(acc[1], ql[ds], kh4[1], kh4[3]);
        }
        int qq = lane >> 2;
#pragma unroll
        for (int j = 0; j < 2; j++) {
            int k = c * 128 + wid * 16 + j * 8 + (lane & 3) * 2;
            u32 u0 = *(const u32*)((const char*)Sb + (((size_t)(q0 + qq) * BHN + bh) * NKV + k) * 2);
            u32 u1 = *(const u32*)((const char*)Sb + (((size_t)(q0 + qq + 8) * BHN + bh) * NKV + k) * 2);
            float2 b0 = __bfloat1622float2(*(__nv_bfloat162*)&u0);
            float2 b1 = __bfloat1622float2(*(__nv_bfloat162*)&u1);
            float2 mm = *(const float2*)&mb[k];
            *(float2*)&S[qq * SROW + k] = make_float2(
                (acc[j][0] + b0.x) * scale + mm.x,
                (acc[j][1] + b0.y) * scale + mm.y);
            *(float2*)&S[(qq + 8) * SROW + k] = make_float2(
                (acc[j][2] + b1.x) * scale + mm.x,
                (acc[j][3] + b1.y) * scale + mm.y);
        }
        __syncthreads();
    }

    // ---- Phase 2: softmax + attn store (2 rows per warp) ----
    for (int r = 0; r < 2; r++) {
        float* row = S + (wid * 2 + r) * SROW;
        float m = -3.4e38f;
        for (int k = lane; k < NKV; k += 32) m = fmaxf(m, row[k]);
#pragma unroll
        for (int o = 16; o; o >>= 1) m = fmaxf(m, __shfl_xor_sync(0xffffffffu, m, o));
        float s = 0.f;
        for (int k = lane; k < NKV; k += 32) {
            float e = __expf(row[k] - m);
            row[k] = e; s += e;
        }
#pragma unroll
        for (int o = 16; o; o >>= 1) s += __shfl_xor_sync(0xffffffffu, s, o);
        float inv = 1.f / s;
        __syncwarp();
        float* arow = attn + ((size_t)bh * NQ + q0 + wid * 2 + r) * NKV;
        for (int k = lane * 4; k < NKV; k += 128) {
            float4 v = *(float4*)&row[k];
            v.x *= inv; v.y *= inv; v.z *= inv; v.w *= inv;
            *(float4*)&row[k] = v;
            *(float4*)&arow[k] = v;
        }
        __syncwarp();
    }
    __syncthreads();

    // ---- Phase 3: ctx = P @ V, 8 chunks of 128 k ----
    float acc[8][4];
#pragma unroll
    for (int j = 0; j < 8; j++)
#pragma unroll
        for (int t = 0; t < 4; t++) acc[j][t] = 0.f;

    for (int c = 0; c < 8; c++) {
        ISSUE_CHUNK(VhB, VlB, c);
        CP_WAIT0();
        __syncthreads();
        u32 bufH = sbp + AS_KB, bufL = bufH + KLO;
        int kbase = c * 128 + wid * 16;

        u32 ph[4], pl[4];
        {
            int r0 = lane >> 2;
            const float* Sr0 = S + r0 * SROW;
            const float* Sr1 = S + (r0 + 8) * SROW;
            int cc = kbase + (lane & 3) * 2;
            split2(*(const float2*)(Sr0 + cc),     ph[0], pl[0]);
            split2(*(const float2*)(Sr1 + cc),     ph[1], pl[1]);
            split2(*(const float2*)(Sr0 + cc + 8), ph[2], pl[2]);
            split2(*(const float2*)(Sr1 + cc + 8), ph[3], pl[3]);
        }
#pragma unroll
        for (int dn = 0; dn < 4; dn++) {
            u32 rv = (u32)((wid * 16 + (lane & 15)) * 72 + dn * 16 + ((lane >> 4) << 3)) * 2;
            u32 vh4[4], vl4[4];
            ldm_x4t(vh4, bufH + rv);
            ldm_x4t(vl4, bufL + rv);
            mma_bf16(acc[dn*2],   ph, vh4[0], vh4[1]);
            mma_bf16(acc[dn*2],   ph, vl4[0], vl4[1]);
            mma_bf16(acc[dn*2],   pl, vh4[0], vh4[1]);
            mma_bf16(acc[dn*2+1], ph, vh4[2], vh4[3]);
            mma_bf16(acc[dn*2+1], ph, vl4[2], vl4[3]);
            mma_bf16(acc[dn*2+1], pl, vh4[2], vh4[3]);
        }
        __syncthreads();
    }

    // slab reduce over 8 warps: slab[w][q][d], stride 68
    float* slab = (float*)(smem + AS_KB);
    {
        int qq = lane >> 2;
#pragma unroll
        for (int j = 0; j < 8; j++) {
            int d = j * 8 + (lane & 3) * 2;
            *(float2*)&slab[(wid * 16 + qq) * 68 + d]     = make_float2(acc[j][0], acc[j][1]);
            *(float2*)&slab[(wid * 16 + qq + 8) * 68 + d] = make_float2(acc[j][2], acc[j][3]);
        }
    }
    __syncthreads();

    {
        int qq = tid >> 4, db = (tid & 15) * 4;
        float s[4] = {0.f, 0.f, 0.f, 0.f};
#pragma unroll
        for (int w = 0; w < 8; w++) {
            const float* p = &slab[(w * 16 + qq) * 68 + db];
#pragma unroll
            for (int t = 0; t < 4; t++) s[t] += p[t];
        }
        float* dst = ctx + ((size_t)b * NQ + q0 + qq) * DM + h * DHD + db;
        *(float4*)dst = make_float4(s[0], s[1], s[2], s[3]);
    }
}

// =====================================================================
// launcher
// =====================================================================
extern "C" void kernel_launch(void* const* d_in, const int* in_sizes, int n_in,
                              void* d_out, int out_size)
{
    const float* q    = (const float*)d_in[0];
    const float* kv   = (const float*)d_in[1];
    const int*   mask = (const int*)  d_in[2];
    const float* Wq   = (const float*)d_in[3];
    const float* bq   = (const float*)d_in[4];
    const float* Wk   = (const float*)d_in[5];
    const float* bk   = (const float*)d_in[6];
    const float* Wv   = (const float*)d_in[7];
    const float* bv   = (const float*)d_in[8];
    const float* Wo   = (const float*)d_in[9];
    const float* bo   = (const float*)d_in[10];
    const float* R    = (const float*)d_in[11];

    float* out = (float*)d_out;
    const size_t out_elems  = (size_t)BB*NQ*DM;
    const size_t attn_elems = (size_t)BHN*NQ*NKV;

    __nv_bfloat16 *Qhh, *Qhl, *Khh, *Khl, *Vhh, *Vhl, *Sb;
    float *ctx, *attn_fb;
    cudaGetSymbolAddress((void**)&Qhh, g_Qhh);
    cudaGetSymbolAddress((void**)&Qhl, g_Qhl);
    cudaGetSymbolAddress((void**)&Khh, g_Khh);
    cudaGetSymbolAddress((void**)&Khl, g_Khl);
    cudaGetSymbolAddress((void**)&Vhh, g_Vhh);
    cudaGetSymbolAddress((void**)&Vhl, g_Vhl);
    cudaGetSymbolAddress((void**)&Sb,  g_Sb);
    cudaGetSymbolAddress((void**)&ctx, g_ctx);
    cudaGetSymbolAddress((void**)&attn_fb, g_attn_fallback);

    float* attn = ((size_t)out_size >= out_elems + attn_elems)
                ? (out + out_elems) : attn_fb;

    cudaFuncSetAttribute(proj_mma, cudaFuncAttributeMaxDynamicSharedMemorySize, PROJ_SMEM);
    cudaFuncSetAttribute(bias_mma, cudaFuncAttributeMaxDynamicSharedMemorySize, BIAS_SMEM);
    cudaFuncSetAttribute(attn_mma, cudaFuncAttributeMaxDynamicSharedMemorySize, ATTN_SMEM);

    dim3 gProj(4, 64);
    proj_mma<<<gProj, 256, PROJ_SMEM>>>(q,  Wq, bq, nullptr, Qhh, Qhl, 1);
    proj_mma<<<gProj, 256, PROJ_SMEM>>>(kv, Wk, bk, nullptr, Khh, Khl, 1);
    proj_mma<<<gProj, 256, PROJ_SMEM>>>(kv, Wv, bv, nullptr, Vhh, Vhl, 1);

    bias_mma<<<dim3(2, 1024), 256, BIAS_SMEM>>>(Qhh, Qhl, R, Sb);

    attn_mma<<<dim3(64, 64), 256, ATTN_SMEM>>>(Qhh, Qhl, Khh, Khl, Vhh, Vhl,
                                               Sb, mask, attn, ctx);

    proj_mma<<<gProj, 256, PROJ_SMEM>>>(ctx, Wo, bo, out, nullptr, nullptr, 0);
}

// round 11
// speedup vs baseline: 2.3589x; 1.0351x over previous
#include <cuda_runtime.h>
#include <cuda_bf16.h>
#include <cstdint>
#include <cstddef>

#define BB    8
#define HH    8
#define NQ    1024
#define NKV   1024
#define DHD   64
#define DM    512
#define BHN   (BB*HH)

typedef unsigned long long ull;
typedef uint32_t u32;

__device__ __forceinline__ u32 smem_u32(const void* p) {
    u32 a;
    asm("{ .reg .u64 t; cvta.to.shared.u64 t, %1; cvt.u32.u64 %0, t; }" : "=r"(a) : "l"(p));
    return a;
}
__device__ __forceinline__ void ldm_x4(u32* r, u32 a) {
    asm volatile("ldmatrix.sync.aligned.m8n8.x4.shared.b16 {%0,%1,%2,%3}, [%4];"
        : "=r"(r[0]),"=r"(r[1]),"=r"(r[2]),"=r"(r[3]) : "r"(a));
}
__device__ __forceinline__ void ldm_x4t(u32* r, u32 a) {
    asm volatile("ldmatrix.sync.aligned.m8n8.x4.trans.shared.b16 {%0,%1,%2,%3}, [%4];"
        : "=r"(r[0]),"=r"(r[1]),"=r"(r[2]),"=r"(r[3]) : "r"(a));
}
__device__ __forceinline__ void mma_bf16(float* c, const u32* a, u32 b0, u32 b1) {
    asm volatile("mma.sync.aligned.m16n8k16.row.col.f32.bf16.bf16.f32 "
        "{%0,%1,%2,%3}, {%4,%5,%6,%7}, {%8,%9}, {%0,%1,%2,%3};"
        : "+f"(c[0]),"+f"(c[1]),"+f"(c[2]),"+f"(c[3])
        : "r"(a[0]),"r"(a[1]),"r"(a[2]),"r"(a[3]), "r"(b0),"r"(b1));
}
__device__ __forceinline__ void split4(float4 v, ull& hi8, ull& lo8) {
    __nv_bfloat162 h01 = __floats2bfloat162_rn(v.x, v.y);
    __nv_bfloat162 h23 = __floats2bfloat162_rn(v.z, v.w);
    float2 f01 = __bfloat1622float2(h01);
    float2 f23 = __bfloat1622float2(h23);
    __nv_bfloat162 l01 = __floats2bfloat162_rn(v.x - f01.x, v.y - f01.y);
    __nv_bfloat162 l23 = __floats2bfloat162_rn(v.z - f23.x, v.w - f23.y);
    u32 uh0 = *(u32*)&h01, uh1 = *(u32*)&h23;
    u32 ul0 = *(u32*)&l01, ul1 = *(u32*)&l23;
    hi8 = (ull)uh0 | ((ull)uh1 << 32);
    lo8 = (ull)ul0 | ((ull)ul1 << 32);
}
__device__ __forceinline__ void split2(float2 v, u32& h, u32& l) {
    __nv_bfloat162 hb = __floats2bfloat162_rn(v.x, v.y);
    float2 hf = __bfloat1622float2(hb);
    __nv_bfloat162 lb = __floats2bfloat162_rn(v.x - hf.x, v.y - hf.y);
    h = *(u32*)&hb; l = *(u32*)&lb;
}
__device__ __forceinline__ u32 pkbf(float x, float y) {
    __nv_bfloat162 t = __floats2bfloat162_rn(x, y);
    return *(u32*)&t;
}

#define CP_ASYNC16(dst, src) \
    asm volatile("cp.async.ca.shared.global [%0], [%1], 16;" :: "r"(dst), "l"(src) : "memory")
#define CP_COMMIT() asm volatile("cp.async.commit_group;" ::: "memory")
#define CP_WAIT0()  asm volatile("cp.async.wait_group 0;" ::: "memory")
#define CP_WAIT1()  asm volatile("cp.async.wait_group 1;" ::: "memory")

// ---------------- device scratch ----------------
__device__ __nv_bfloat16 g_Qhh[(size_t)BHN*NQ*DHD];
__device__ __nv_bfloat16 g_Qhl[(size_t)BHN*NQ*DHD];
__device__ __nv_bfloat16 g_Khh[(size_t)BHN*NKV*DHD];
__device__ __nv_bfloat16 g_Khl[(size_t)BHN*NKV*DHD];
__device__ __nv_bfloat16 g_Vhh[(size_t)BHN*NKV*DHD];
__device__ __nv_bfloat16 g_Vhl[(size_t)BHN*NKV*DHD];
__device__ __nv_bfloat16 g_Sb[(size_t)NQ*BHN*NKV];
__device__ __nv_bfloat16 g_qh[(size_t)BB*NQ*DM],  g_ql[(size_t)BB*NQ*DM];
__device__ __nv_bfloat16 g_kvh[(size_t)BB*NKV*DM], g_kvl[(size_t)BB*NKV*DM];
__device__ __nv_bfloat16 g_ch[(size_t)BB*NQ*DM],  g_cl[(size_t)BB*NQ*DM];
__device__ __nv_bfloat16 g_Wh[(size_t)4*DM*DM],   g_Wl[(size_t)4*DM*DM];
__device__ float g_attn_fallback[(size_t)BHN*NQ*NKV];

// =====================================================================
// cvt: fp32 -> bf16 hi/lo split (grid-stride over float4s)
// =====================================================================
__global__ void cvt(const float* __restrict__ x,
                    __nv_bfloat16* __restrict__ h, __nv_bfloat16* __restrict__ l, int n4)
{
    int i = blockIdx.x * blockDim.x + threadIdx.x;
    if (i < n4) {
        float4 v = ((const float4*)x)[i];
        ull h8, l8; split4(v, h8, l8);
        ((ull*)h)[i] = h8;
        ((ull*)l)[i] = l8;
    }
}

// =====================================================================
// proj_bf: C[8192x512] = A @ W + bias, A/W pre-split bf16 hi/lo.
// cp.async double-buffered K-chunks of 64. 128x128 tile, 8 warps.
// smem per stage: AH [128][72]e=18432B  AL 18432  WH [64][136]e=17408  WL 17408
// =====================================================================
#define PB_AH 0
#define PB_AL 18432
#define PB_WH 36864
#define PB_WL 54272
#define PB_STAGE 71680
#define PROJB_SMEM (2*PB_STAGE)

__global__ __launch_bounds__(256) void proj_bf(
    const __nv_bfloat16* __restrict__ Ah, const __nv_bfloat16* __restrict__ Al,
    const __nv_bfloat16* __restrict__ Wh, const __nv_bfloat16* __restrict__ Wl,
    const float* __restrict__ bias, float* __restrict__ C,
    __nv_bfloat16* __restrict__ Ohi, __nv_bfloat16* __restrict__ Olo,
    int permute)
{
    extern __shared__ __align__(128) char smem[];
    u32 sb = smem_u32(smem);
    int tid = threadIdx.x, wid = tid >> 5, lane = tid & 31;
    int m0 = blockIdx.y * 128, n0 = blockIdx.x * 128;
    int wm = wid & 3, wn = wid >> 2;

    int arow = tid >> 3, ac16 = tid & 7;      // A copy: 32 rows/iter x 8 cols16
    int wrow = tid >> 4, wc16 = tid & 15;     // W copy: 16 rows/iter x 16 cols16

#define PB_ISSUE(kb, buf) do {                                                       \
        u32 base_ = sb + (buf) * PB_STAGE;                                           \
        _Pragma("unroll")                                                            \
        for (int r_ = 0; r_ < 4; r_++) {                                             \
            int row_ = arow + r_ * 32;                                               \
            u32 d_ = base_ + (u32)(row_ * 144 + ac16 * 16);                          \
            size_t s_ = ((size_t)(m0 + row_) * 512 + (kb) * 64 + ac16 * 8) * 2;      \
            CP_ASYNC16(d_ + PB_AH, (const char*)Ah + s_);                            \
            CP_ASYNC16(d_ + PB_AL, (const char*)Al + s_);                            \
        }                                                                            \
        _Pragma("unroll")                                                            \
        for (int r_ = 0; r_ < 4; r_++) {                                             \
            int row_ = wrow + r_ * 16;                                               \
            u32 d_ = base_ + (u32)(row_ * 272 + wc16 * 16);                          \
            size_t s_ = ((size_t)((kb) * 64 + row_) * 512 + n0 + wc16 * 8) * 2;      \
            CP_ASYNC16(d_ + PB_WH, (const char*)Wh + s_);                            \
            CP_ASYNC16(d_ + PB_WL, (const char*)Wl + s_);                            \
        }                                                                            \
        CP_COMMIT();                                                                 \
    } while (0)

    float acc[2][8][4];
#pragma unroll
    for (int m = 0; m < 2; m++)
#pragma unroll
        for (int j = 0; j < 8; j++)
#pragma unroll
            for (int t = 0; t < 4; t++) acc[m][j][t] = 0.f;

    PB_ISSUE(0, 0);
    for (int kb = 0; kb < 8; kb++) {
        if (kb < 7) { PB_ISSUE(kb + 1, (kb + 1) & 1); CP_WAIT1(); }
        else CP_WAIT0();
        __syncthreads();
        u32 base = sb + (kb & 1) * PB_STAGE;

#pragma unroll
        for (int ks = 0; ks < 4; ks++) {
            u32 ah[2][4], al[2][4];
#pragma unroll
            for (int f = 0; f < 2; f++) {
                u32 ra = base + PB_AH
                       + (u32)((wm * 32 + f * 16 + (lane & 15)) * 144 + (ks * 16 + ((lane >> 4) << 3)) * 2);
                ldm_x4(ah[f], ra);
                ldm_x4(al[f], ra + (PB_AL - PB_AH));
            }
#pragma unroll
            for (int nf = 0; nf < 4; nf++) {
                u32 rb = base + PB_WH
                       + (u32)((ks * 16 + (lane & 15)) * 272 + (wn * 64 + nf * 16 + ((lane >> 4) << 3)) * 2);
                u32 bh4[4], bl4[4];
                ldm_x4t(bh4, rb);
                ldm_x4t(bl4, rb + (PB_WL - PB_WH));
#pragma unroll
                for (int m = 0; m < 2; m++) {
                    mma_bf16(acc[m][nf*2],   ah[m], bh4[0], bh4[1]);
                    mma_bf16(acc[m][nf*2],   ah[m], bl4[0], bl4[1]);
                    mma_bf16(acc[m][nf*2],   al[m], bh4[0], bh4[1]);
                    mma_bf16(acc[m][nf*2+1], ah[m], bh4[2], bh4[3]);
                    mma_bf16(acc[m][nf*2+1], ah[m], bl4[2], bl4[3]);
                    mma_bf16(acc[m][nf*2+1], al[m], bh4[2], bh4[3]);
                }
            }
        }
        __syncthreads();
    }

    int r0 = m0 + wm * 32 + (lane >> 2);
    int cb = n0 + wn * 64 + (lane & 3) * 2;
#pragma unroll
    for (int m = 0; m < 2; m++) {
#pragma unroll
        for (int j = 0; j < 8; j++) {
            int col = cb + j * 8;
            float2 bv = *(const float2*)&bias[col];
            int rowA = r0 + m * 16, rowB = rowA + 8;
            float2 vA = make_float2(acc[m][j][0] + bv.x, acc[m][j][1] + bv.y);
            float2 vB = make_float2(acc[m][j][2] + bv.x, acc[m][j][3] + bv.y);
            if (permute) {
                int h = col >> 6, dd = col & 63;
                size_t eA = ((size_t)((rowA >> 10) * HH + h) * NQ + (rowA & 1023)) * 64 + dd;
                size_t eB = ((size_t)((rowB >> 10) * HH + h) * NQ + (rowB & 1023)) * 64 + dd;
                u32 hA, lA, hB, lB;
                split2(vA, hA, lA); split2(vB, hB, lB);
                *(u32*)((char*)Ohi + eA * 2) = hA;
                *(u32*)((char*)Olo + eA * 2) = lA;
                *(u32*)((char*)Ohi + eB * 2) = hB;
                *(u32*)((char*)Olo + eB * 2) = lB;
            } else {
                *(float2*)(C + (size_t)rowA * 512 + col) = vA;
                *(float2*)(C + (size_t)rowB * 512 + col) = vB;
            }
        }
    }
}

// =====================================================================
// bias_mma: unchanged (round-10, passing).
// =====================================================================
#define BZ_RH 0
#define BZ_QH 36864
#define BZ_QL 46080
#define BIAS_SMEM 55296

__global__ __launch_bounds__(256) void bias_mma(
    const __nv_bfloat16* __restrict__ Qhh, const __nv_bfloat16* __restrict__ Qhl,
    const float* __restrict__ R, __nv_bfloat16* __restrict__ Sb)
{
    extern __shared__ __align__(128) char smem[];
    u32 sb = smem_u32(smem);
    int tid = threadIdx.x, wid = tid >> 5, lane = tid & 31;
    int wm = wid & 3, wn = wid >> 2;
    int q = blockIdx.y, kc = blockIdx.x;

#pragma unroll
    for (int r = 0; r < 2; r++) {
        int idx = tid + r * 256;
        int row = idx >> 3, c4 = idx & 7;
        u32 off = (u32)(row * 144 + c4 * 16);
        size_t e = ((size_t)row * NQ + q) * DHD + c4 * 8;
        *(uint4*)(smem + BZ_QH + off) = *(const uint4*)((const char*)Qhh + e * 2);
        *(uint4*)(smem + BZ_QL + off) = *(const uint4*)((const char*)Qhl + e * 2);
    }
    __syncthreads();

    u32 qh4[4][2][4], ql4[4][2][4];
#pragma unroll
    for (int ks = 0; ks < 4; ks++)
#pragma unroll
        for (int g = 0; g < 2; g++) {
            u32 rb = (u32)((wn * 32 + g * 16 + (lane & 7) + ((lane >> 4) << 3)) * 72
                           + ks * 16 + (((lane >> 3) & 1) << 3)) * 2;
            ldm_x4(qh4[ks][g], sb + BZ_QH + rb);
            ldm_x4(ql4[ks][g], sb + BZ_QL + rb);
        }

    for (int kt = 0; kt < 4; kt++) {
        int k0 = (kc * 4 + kt) * 128;
#pragma unroll
        for (int r = 0; r < 8; r++) {
            int idx = tid + r * 256;
            int row = idx >> 4, col = (idx & 15) << 2;
            float4 v = *(const float4*)(R + ((size_t)q * NKV + k0 + row) * DHD + col);
            u32 p0 = pkbf(v.x, v.y), p1 = pkbf(v.z, v.w);
            *(ull*)(smem + BZ_RH + (row * 72 + col) * 2) = (ull)p0 | ((ull)p1 << 32);
        }
        __syncthreads();

        float acc[2][4][4];
#pragma unroll
        for (int m = 0; m < 2; m++)
#pragma unroll
            for (int j = 0; j < 4; j++)
#pragma unroll
                for (int t = 0; t < 4; t++) acc[m][j][t] = 0.f;

#pragma unroll
        for (int ks = 0; ks < 4; ks++) {
            u32 ah[2][4];
#pragma unroll
            for (int f = 0; f < 2; f++) {
                u32 ra = (u32)((wm * 32 + f * 16 + (lane & 15)) * 72 + ks * 16 + ((lane >> 4) << 3)) * 2;
                ldm_x4(ah[f], sb + BZ_RH + ra);
            }
#pragma unroll
            for (int g = 0; g < 2; g++)
#pragma unroll
                for (int m = 0; m < 2; m++) {
                    mma_bf16(acc[m][g*2],   ah[m], qh4[ks][g][0], qh4[ks][g][1]);
                    mma_bf16(acc[m][g*2],   ah[m], ql4[ks][g][0], ql4[ks][g][1]);
                    mma_bf16(acc[m][g*2+1], ah[m], qh4[ks][g][2], qh4[ks][g][3]);
                    mma_bf16(acc[m][g*2+1], ah[m], ql4[ks][g][2], ql4[ks][g][3]);
                }
        }
        __syncthreads();

        float* T = (float*)smem;
#pragma unroll
        for (int m = 0; m < 2; m++) {
            int krow = wm * 32 + m * 16 + (lane >> 2);
#pragma unroll
            for (int j = 0; j < 4; j++) {
                int bhc = wn * 32 + j * 8 + (lane & 3) * 2;
                T[bhc * 132 + krow]           = acc[m][j][0];
                T[(bhc + 1) * 132 + krow]     = acc[m][j][1];
                T[bhc * 132 + krow + 8]       = acc[m][j][2];
                T[(bhc + 1) * 132 + krow + 8] = acc[m][j][3];
            }
        }
        __syncthreads();

        int bh2 = tid >> 2, part = tid & 3;
        size_t dbase = ((size_t)q * BHN + bh2) * NKV + k0 + part * 32;
#pragma unroll
        for (int j = 0; j < 4; j++) {
            float4 a = *(float4*)&T[bh2 * 132 + part * 32 + j * 8];
            float4 b = *(float4*)&T[bh2 * 132 + part * 32 + j * 8 + 4];
            uint4 o;
            o.x = pkbf(a.x, a.y); o.y = pkbf(a.z, a.w);
            o.z = pkbf(b.x, b.y); o.w = pkbf(b.z, b.w);
            *(uint4*)((char*)Sb + (dbase + j * 8) * 2) = o;
        }
        __syncthreads();
    }
}

// =====================================================================
// attn_mma: round-10 version; epilogue writes ctx as bf16 hi/lo.
// =====================================================================
#define SROW  1028
#define AS_MB 65792
#define AS_QH 69888
#define AS_QL 72192
#define AS_KB 74496
#define KLO   18432
#define ATTN_SMEM 111360

__global__ __launch_bounds__(256, 2) void attn_mma(
    const __nv_bfloat16* __restrict__ Qhh, const __nv_bfloat16* __restrict__ Qhl,
    const __nv_bfloat16* __restrict__ Khh, const __nv_bfloat16* __restrict__ Khl,
    const __nv_bfloat16* __restrict__ Vhh, const __nv_bfloat16* __restrict__ Vhl,
    const __nv_bfloat16* __restrict__ Sb,
    const int* __restrict__ mask, float* __restrict__ attn,
    __nv_bfloat16* __restrict__ Ch, __nv_bfloat16* __restrict__ Cl)
{
    extern __shared__ __align__(128) char smem[];
    u32 sbp = smem_u32(smem);
    float* S  = (float*)smem;
    float* mb = (float*)(smem + AS_MB);
    int tid = threadIdx.x, wid = tid >> 5, lane = tid & 31;
    int bh  = blockIdx.x;
    int q0  = blockIdx.y * 16;
    int b = bh >> 3, h = bh & 7;
    const float scale = 0.125f;

    const __nv_bfloat16* KhB = Khh + (size_t)bh * NKV * DHD;
    const __nv_bfloat16* KlB = Khl + (size_t)bh * NKV * DHD;
    const __nv_bfloat16* VhB = Vhh + (size_t)bh * NKV * DHD;
    const __nv_bfloat16* VlB = Vhl + (size_t)bh * NKV * DHD;

    if (tid < 128) {
        int row = tid >> 3, c4 = tid & 7;
        u32 off = (u32)(row * 144 + c4 * 16);
        size_t e = ((size_t)bh * NQ + q0 + row) * DHD + c4 * 8;
        *(uint4*)(smem + AS_QH + off) = *(const uint4*)((const char*)Qhh + e * 2);
        *(uint4*)(smem + AS_QL + off) = *(const uint4*)((const char*)Qhl + e * 2);
    }
    for (int k = tid; k < NKV; k += 256)
        mb[k] = mask[b * NKV + k] ? 0.f : -1e30f;
    __syncthreads();

    u32 qh[4][4], ql[4][4];
#pragma unroll
    for (int ds = 0; ds < 4; ds++) {
        u32 ra = (u32)((lane & 15) * 72 + ds * 16 + ((lane >> 4) << 3)) * 2;
        ldm_x4(qh[ds], sbp + AS_QH + ra);
        ldm_x4(ql[ds], sbp + AS_QL + ra);
    }

    int prow = tid >> 3, pc4 = tid & 7;
    u32 poff0 = (u32)(prow * 144 + pc4 * 16);
    size_t psrc0 = (size_t)prow * 64 + pc4 * 8;

#define ISSUE_CHUNK(HIptr, LOptr, cix) do {                                        \
        u32 dh_ = sbp + AS_KB;                                                     \
        u32 dl_ = dh_ + KLO;                                                       \
        const char* sh_ = (const char*)((HIptr) + (size_t)(cix) * 128 * 64);       \
        const char* sl_ = (const char*)((LOptr) + (size_t)(cix) * 128 * 64);       \
        _Pragma("unroll")                                                          \
        for (int r_ = 0; r_ < 4; r_++) {                                           \
            u32 o_ = poff0 + (u32)r_ * 32 * 144;                                   \
            size_t s_ = (psrc0 + (size_t)r_ * 32 * 64) * 2;                        \
            CP_ASYNC16(dh_ + o_, sh_ + s_);                                        \
            CP_ASYNC16(dl_ + o_, sl_ + s_);                                        \
        }                                                                          \
        CP_COMMIT();                                                               \
    } while (0)

    // ---- Phase 1: QK^T + Sb + mask ----
    for (int c = 0; c < 8; c++) {
        ISSUE_CHUNK(KhB, KlB, c);
        CP_WAIT0();
        __syncthreads();
        u32 bufH = sbp + AS_KB, bufL = bufH + KLO;

        float acc[2][4];
#pragma unroll
        for (int j = 0; j < 2; j++)
#pragma unroll
            for (int t = 0; t < 4; t++) acc[j][t] = 0.f;

#pragma unroll
        for (int ds = 0; ds < 4; ds++) {
            u32 rb = (u32)((wid * 16 + (lane & 15)) * 72 + ds * 16 + ((lane >> 4) << 3)) * 2;
            u32 kh4[4], kl4[4];
            ldm_x4(kh4, bufH + rb);
            ldm_x4(kl4, bufL + rb);
            mma_bf16(acc[0], qh[ds], kh4[0], kh4[2]);
            mma_bf16(acc[0], qh[ds], kl4[0], kl4[2]);
            mma_bf16(acc[0], ql[ds], kh4[0], kh4[2]);
            mma_bf16(acc[1], qh[ds], kh4[1], kh4[3]);
            mma_bf16(acc[1], qh[ds], kl4[1], kl4[3]);
            mma_bf16(acc[1], ql[ds], kh4[1], kh4[3]);
        }
        int qq = lane >> 2;
#pragma unroll
        for (int j = 0; j < 2; j++) {
            int k = c * 128 + wid * 16 + j * 8 + (lane & 3) * 2;
            u32 u0 = *(const u32*)((const char*)Sb + (((size_t)(q0 + qq) * BHN + bh) * NKV + k) * 2);
            u32 u1 = *(const u32*)((const char*)Sb + (((size_t)(q0 + qq + 8) * BHN + bh) * NKV + k) * 2);
            float2 b0 = __bfloat1622float2(*(__nv_bfloat162*)&u0);
            float2 b1 = __bfloat1622float2(*(__nv_bfloat162*)&u1);
            float2 mm = *(const float2*)&mb[k];
            *(float2*)&S[qq * SROW + k] = make_float2(
                (acc[j][0] + b0.x) * scale + mm.x,
                (acc[j][1] + b0.y) * scale + mm.y);
            *(float2*)&S[(qq + 8) * SROW + k] = make_float2(
                (acc[j][2] + b1.x) * scale + mm.x,
                (acc[j][3] + b1.y) * scale + mm.y);
        }
        __syncthreads();
    }

    // ---- Phase 2: softmax + attn store ----
    for (int r = 0; r < 2; r++) {
        float* row = S + (wid * 2 + r) * SROW;
        float m = -3.4e38f;
        for (int k = lane; k < NKV; k += 32) m = fmaxf(m, row[k]);
#pragma unroll
        for (int o = 16; o; o >>= 1) m = fmaxf(m, __shfl_xor_sync(0xffffffffu, m, o));
        float s = 0.f;
        for (int k = lane; k < NKV; k += 32) {
            float e = __expf(row[k] - m);
            row[k] = e; s += e;
        }
#pragma unroll
        for (int o = 16; o; o >>= 1) s += __shfl_xor_sync(0xffffffffu, s, o);
        float inv = 1.f / s;
        __syncwarp();
        float* arow = attn + ((size_t)bh * NQ + q0 + wid * 2 + r) * NKV;
        for (int k = lane * 4; k < NKV; k += 128) {
            float4 v = *(float4*)&row[k];
            v.x *= inv; v.y *= inv; v.z *= inv; v.w *= inv;
            *(float4*)&row[k] = v;
            *(float4*)&arow[k] = v;
        }
        __syncwarp();
    }
    __syncthreads();

    // ---- Phase 3: ctx = P @ V ----
    float acc[8][4];
#pragma unroll
    for (int j = 0; j < 8; j++)
#pragma unroll
        for (int t = 0; t < 4; t++) acc[j][t] = 0.f;

    for (int c = 0; c < 8; c++) {
        ISSUE_CHUNK(VhB, VlB, c);
        CP_WAIT0();
        __syncthreads();
        u32 bufH = sbp + AS_KB, bufL = bufH + KLO;
        int kbase = c * 128 + wid * 16;

        u32 ph[4], pl[4];
        {
            int r0 = lane >> 2;
            const float* Sr0 = S + r0 * SROW;
            const float* Sr1 = S + (r0 + 8) * SROW;
            int cc = kbase + (lane & 3) * 2;
            split2(*(const float2*)(Sr0 + cc),     ph[0], pl[0]);
            split2(*(const float2*)(Sr1 + cc),     ph[1], pl[1]);
            split2(*(const float2*)(Sr0 + cc + 8), ph[2], pl[2]);
            split2(*(const float2*)(Sr1 + cc + 8), ph[3], pl[3]);
        }
#pragma unroll
        for (int dn = 0; dn < 4; dn++) {
            u32 rv = (u32)((wid * 16 + (lane & 15)) * 72 + dn * 16 + ((lane >> 4) << 3)) * 2;
            u32 vh4[4], vl4[4];
            ldm_x4t(vh4, bufH + rv);
            ldm_x4t(vl4, bufL + rv);
            mma_bf16(acc[dn*2],   ph, vh4[0], vh4[1]);
            mma_bf16(acc[dn*2],   ph, vl4[0], vl4[1]);
            mma_bf16(acc[dn*2],   pl, vh4[0], vh4[1]);
            mma_bf16(acc[dn*2+1], ph, vh4[2], vh4[3]);
            mma_bf16(acc[dn*2+1], ph, vl4[2], vl4[3]);
            mma_bf16(acc[dn*2+1], pl, vh4[2], vh4[3]);
        }
        __syncthreads();
    }

    float* slab = (float*)(smem + AS_KB);
    {
        int qq = lane >> 2;
#pragma unroll
        for (int j = 0; j < 8; j++) {
            int d = j * 8 + (lane & 3) * 2;
            *(float2*)&slab[(wid * 16 + qq) * 68 + d]     = make_float2(acc[j][0], acc[j][1]);
            *(float2*)&slab[(wid * 16 + qq + 8) * 68 + d] = make_float2(acc[j][2], acc[j][3]);
        }
    }
    __syncthreads();

    {
        int qq = tid >> 4, db = (tid & 15) * 4;
        float s[4] = {0.f, 0.f, 0.f, 0.f};
#pragma unroll
        for (int w = 0; w < 8; w++) {
            const float* p = &slab[(w * 16 + qq) * 68 + db];
#pragma unroll
            for (int t = 0; t < 4; t++) s[t] += p[t];
        }
        size_t e = ((size_t)b * NQ + q0 + qq) * DM + h * DHD + db;
        u32 h0, l0, h1, l1;
        split2(make_float2(s[0], s[1]), h0, l0);
        split2(make_float2(s[2], s[3]), h1, l1);
        *(u32*)((char*)Ch + e * 2)     = h0;
        *(u32*)((char*)Ch + e * 2 + 4) = h1;
        *(u32*)((char*)Cl + e * 2)     = l0;
        *(u32*)((char*)Cl + e * 2 + 4) = l1;
    }
}

// =====================================================================
// launcher
// =====================================================================
extern "C" void kernel_launch(void* const* d_in, const int* in_sizes, int n_in,
                              void* d_out, int out_size)
{
    const float* q    = (const float*)d_in[0];
    const float* kv   = (const float*)d_in[1];
    const int*   mask = (const int*)  d_in[2];
    const float* Wq   = (const float*)d_in[3];
    const float* bq   = (const float*)d_in[4];
    const float* Wk   = (const float*)d_in[5];
    const float* bk   = (const float*)d_in[6];
    const float* Wv   = (const float*)d_in[7];
    const float* bv   = (const float*)d_in[8];
    const float* Wo   = (const float*)d_in[9];
    const float* bo   = (const float*)d_in[10];
    const float* R    = (const float*)d_in[11];

    float* out = (float*)d_out;
    const size_t out_elems  = (size_t)BB*NQ*DM;
    const size_t attn_elems = (size_t)BHN*NQ*NKV;

    __nv_bfloat16 *Qhh, *Qhl, *Khh, *Khl, *Vhh, *Vhl, *Sb;
    __nv_bfloat16 *qh, *ql2, *kvh, *kvl, *ch, *cl, *Wh, *Wl;
    float *attn_fb;
    cudaGetSymbolAddress((void**)&Qhh, g_Qhh);
    cudaGetSymbolAddress((void**)&Qhl, g_Qhl);
    cudaGetSymbolAddress((void**)&Khh, g_Khh);
    cudaGetSymbolAddress((void**)&Khl, g_Khl);
    cudaGetSymbolAddress((void**)&Vhh, g_Vhh);
    cudaGetSymbolAddress((void**)&Vhl, g_Vhl);
    cudaGetSymbolAddress((void**)&Sb,  g_Sb);
    cudaGetSymbolAddress((void**)&qh,  g_qh);
    cudaGetSymbolAddress((void**)&ql2, g_ql);
    cudaGetSymbolAddress((void**)&kvh, g_kvh);
    cudaGetSymbolAddress((void**)&kvl, g_kvl);
    cudaGetSymbolAddress((void**)&ch,  g_ch);
    cudaGetSymbolAddress((void**)&cl,  g_cl);
    cudaGetSymbolAddress((void**)&Wh,  g_Wh);
    cudaGetSymbolAddress((void**)&Wl,  g_Wl);
    cudaGetSymbolAddress((void**)&attn_fb, g_attn_fallback);

    float* attn = ((size_t)out_size >= out_elems + attn_elems)
                ? (out + out_elems) : attn_fb;

    cudaFuncSetAttribute(proj_bf,  cudaFuncAttributeMaxDynamicSharedMemorySize, PROJB_SMEM);
    cudaFuncSetAttribute(bias_mma, cudaFuncAttributeMaxDynamicSharedMemorySize, BIAS_SMEM);
    cudaFuncSetAttribute(attn_mma, cudaFuncAttributeMaxDynamicSharedMemorySize, ATTN_SMEM);

    const size_t WSZ = (size_t)DM * DM;   // 262144
    // conversions
    cvt<<<4096, 256>>>(q,  qh,  ql2, (int)(out_elems / 4));
    cvt<<<4096, 256>>>(kv, kvh, kvl, (int)(out_elems / 4));
    cvt<<<256, 256>>>(Wq, Wh + 0*WSZ, Wl + 0*WSZ, (int)(WSZ / 4));
    cvt<<<256, 256>>>(Wk, Wh + 1*WSZ, Wl + 1*WSZ, (int)(WSZ / 4));
    cvt<<<256, 256>>>(Wv, Wh + 2*WSZ, Wl + 2*WSZ, (int)(WSZ / 4));
    cvt<<<256, 256>>>(Wo, Wh + 3*WSZ, Wl + 3*WSZ, (int)(WSZ / 4));

    dim3 gProj(4, 64);
    proj_bf<<<gProj, 256, PROJB_SMEM>>>(qh,  ql2, Wh + 0*WSZ, Wl + 0*WSZ, bq, nullptr, Qhh, Qhl, 1);
    proj_bf<<<gProj, 256, PROJB_SMEM>>>(kvh, kvl, Wh + 1*WSZ, Wl + 1*WSZ, bk, nullptr, Khh, Khl, 1);
    proj_bf<<<gProj, 256, PROJB_SMEM>>>(kvh, kvl, Wh + 2*WSZ, Wl + 2*WSZ, bv, nullptr, Vhh, Vhl, 1);

    bias_mma<<<dim3(2, 1024), 256, BIAS_SMEM>>>(Qhh, Qhl, R, Sb);

    attn_mma<<<dim3(64, 64), 256, ATTN_SMEM>>>(Qhh, Qhl, Khh, Khl, Vhh, Vhl,
                                               Sb, mask, attn, ch, cl);

    proj_bf<<<gProj, 256, PROJB_SMEM>>>(ch, cl, Wh + 3*WSZ, Wl + 3*WSZ, bo, out, nullptr, nullptr, 0);
}